// round 15
// baseline (speedup 1.0000x reference)
#include <cuda_runtime.h>
#include <cstddef>

// ---------------------------------------------------------------------------
// Sinkhorn divergence (geomloss p=2, blur=0.05, scaling=0.5, diameter=32)
// N = M = 8192, D = 64.  R15:
// Mode A (factored exp, 1 ex2/elem, MUFU floor) for eps >= 1.
// Mode C (NEW) for eps < 1: exact per-row AND per-column anchors computed in
// a first register pass (fmaf/max only), then 2 ex2/elem sums — branchless,
// safe at any eps (flushed terms < 2^-126 of their own row/col max).
// All sparse-list / drift / collect machinery deleted.
// ---------------------------------------------------------------------------

#define NPTS 8192
#define DIMS 64
#define NN      ((size_t)NPTS * (size_t)NPTS)
#define NCHUNK  64
#define QSCALE  128.0f
#define QINV    (1.0f / 128.0f)
#define NTILES_XY  4096
#define NTILES_SYM 2080
#define NTILES_ALL (NTILES_XY + 2 * NTILES_SYM)

#define LOG2E_F 1.4426950408889634f
#define LN2_F   0.6931471805599453f
#define NEG_LOG_N_F (-9.010913347279288f)   // -ln(8192)
#define KB_CONST (NEG_LOG_N_F * LOG2E_F)
#define NSLOTS 14

__device__ __align__(256) unsigned short d_cq[3 * NN];               // 384 MB
__device__ __align__(256) float2 d_part[4 * (size_t)NCHUNK * NPTS];  // 16 MB
__device__ __align__(256) float  d_tilemin[3 * 4096];
__device__ __align__(256) float  d_vecbuf[11 * NPTS];
__device__ __align__(256) unsigned d_stat_max[NSLOTS * 4];

#define V_HX 0
#define V_HY 1
#define V_ZERO 2
#define V_FAA 3
#define V_GBB 4
#define V_GAB 5
#define V_FBA 6
#define V_FT 7
#define V_GT 8
#define V_FS 9
#define V_GS 10

__device__ __forceinline__ float ex2_fast(float x) {
    float r; asm("ex2.approx.ftz.f32 %0, %1;" : "=f"(r) : "f"(x)); return r;
}
__device__ __forceinline__ float lg2_fast(float x) {
    float r; asm("lg2.approx.f32 %0, %1;" : "=f"(r) : "f"(x)); return r;
}
__device__ __forceinline__ float dec_lo(unsigned w) {
    return __uint_as_float(__byte_perm(w, 0x4B000000u, 0x7410)) - 8388608.0f;
}
__device__ __forceinline__ float dec_hi(unsigned w) {
    return __uint_as_float(__byte_perm(w, 0x4B000000u, 0x7432)) - 8388608.0f;
}
__device__ __forceinline__ unsigned enc_f(float f) {
    unsigned u = __float_as_uint(f);
    return (u & 0x80000000u) ? ~u : (u | 0x80000000u);
}
__device__ __forceinline__ float dec_f(unsigned u) {
    return __uint_as_float((u & 0x80000000u) ? (u ^ 0x80000000u) : ~u);
}

// ---------------------------------------------------------------------------
__global__ void init_misc_kernel() {
    int idx = threadIdx.x;
    if (idx < NSLOTS * 4) d_stat_max[idx] = enc_f(-3e38f);
    if (idx < 4) d_stat_max[idx] = enc_f(0.0f);   // slot 0: zero potentials
}

__global__ void prep_kernel(const float* __restrict__ x, const float* __restrict__ y,
                            float* __restrict__ hx, float* __restrict__ hy) {
    int gw = (blockIdx.x * blockDim.x + threadIdx.x) >> 5;
    int lane = threadIdx.x & 31;
    const float* X = (gw < NPTS) ? x : y;
    float* H = (gw < NPTS) ? hx : hy;
    int row = (gw < NPTS) ? gw : gw - NPTS;
    float v0 = X[(size_t)row * DIMS + lane];
    float v1 = X[(size_t)row * DIMS + 32 + lane];
    float s = v0 * v0 + v1 * v1;
    #pragma unroll
    for (int o = 16; o > 0; o >>= 1) s += __shfl_xor_sync(0xffffffffu, s, o);
    if (lane == 0) H[row] = 0.5f * s;
}

// ---------------------------------------------------------------------------
// merged GEMM: z=0 Cxy, z=1 Cxx upper, z=2 Cyy upper; u16 quant + tile min.
// ---------------------------------------------------------------------------
__global__ void __launch_bounds__(256)
gemm_cost_q(const float* __restrict__ x, const float* __restrict__ y,
            const float* __restrict__ hx, const float* __restrict__ hy,
            unsigned short* __restrict__ cq, float* __restrict__ tmin) {
    const int mz = blockIdx.z;
    int bi = blockIdx.y, bj = blockIdx.x;
    if (mz > 0 && bi > bj) return;
    const float* A  = (mz == 2) ? y : x;
    const float* B  = (mz == 0 || mz == 2) ? y : x;
    const float* ha = (mz == 2) ? hy : hx;
    const float* hb = (mz == 0 || mz == 2) ? hy : hx;
    unsigned short* C = cq + (size_t)mz * NN;
    float* tileminf = tmin + mz * 4096;

    const int i0 = bi * 128, j0 = bj * 128;
    __shared__ float As[32][132];
    __shared__ float Bs[32][132];
    __shared__ unsigned sm_min[8];

    const int tid = threadIdx.x;
    const int lane = tid & 31, warp = tid >> 5;
    const int wy = warp >> 1, wx = warp & 1;
    const int ty2 = lane & 3, tx2 = lane >> 2;
    const int r0 = wy * 32 + ty2 * 8;
    const int c0 = wx * 64 + tx2 * 8;

    float acc[8][8];
    #pragma unroll
    for (int p = 0; p < 8; p++)
        #pragma unroll
        for (int q = 0; q < 8; q++) acc[p][q] = 0.0f;

    #pragma unroll
    for (int kc = 0; kc < 2; kc++) {
        #pragma unroll
        for (int u = 0; u < 4; u++) {
            int idx = tid + 256 * u;
            int row = idx >> 3, kq = idx & 7;
            float4 av = *(const float4*)(A + (size_t)(i0 + row) * DIMS + kc * 32 + kq * 4);
            float4 bv = *(const float4*)(B + (size_t)(j0 + row) * DIMS + kc * 32 + kq * 4);
            As[kq * 4 + 0][row] = av.x; As[kq * 4 + 1][row] = av.y;
            As[kq * 4 + 2][row] = av.z; As[kq * 4 + 3][row] = av.w;
            Bs[kq * 4 + 0][row] = bv.x; Bs[kq * 4 + 1][row] = bv.y;
            Bs[kq * 4 + 2][row] = bv.z; Bs[kq * 4 + 3][row] = bv.w;
        }
        __syncthreads();
        #pragma unroll 4
        for (int k = 0; k < 32; k++) {
            float a[8], b[8];
            *(float4*)&a[0] = *(const float4*)&As[k][r0];
            *(float4*)&a[4] = *(const float4*)&As[k][r0 + 4];
            *(float4*)&b[0] = *(const float4*)&Bs[k][c0];
            *(float4*)&b[4] = *(const float4*)&Bs[k][c0 + 4];
            #pragma unroll
            for (int p = 0; p < 8; p++)
                #pragma unroll
                for (int q = 0; q < 8; q++)
                    acc[p][q] = fmaf(a[p], b[q], acc[p][q]);
        }
        __syncthreads();
    }

    float hav[8], hbv[8];
    #pragma unroll
    for (int p = 0; p < 8; p++) hav[p] = ha[i0 + r0 + p];
    #pragma unroll
    for (int q = 0; q < 8; q++) hbv[q] = hb[j0 + c0 + q];

    unsigned tvmin = 0xFFFFu;
    #pragma unroll
    for (int p = 0; p < 8; p++) {
        unsigned v[8];
        #pragma unroll
        for (int q = 0; q < 8; q++) {
            float val = fmaxf(hav[p] + hbv[q] - acc[p][q], 0.0f) * QSCALE;
            unsigned xq = __float2uint_rn(val);
            v[q] = xq > 65535u ? 65535u : xq;
            tvmin = min(tvmin, v[q]);
        }
        uint4 w;
        w.x = v[0] | (v[1] << 16); w.y = v[2] | (v[3] << 16);
        w.z = v[4] | (v[5] << 16); w.w = v[6] | (v[7] << 16);
        *(uint4*)(C + (size_t)(i0 + r0 + p) * NPTS + j0 + c0) = w;
    }
    #pragma unroll
    for (int o = 16; o > 0; o >>= 1)
        tvmin = min(tvmin, __shfl_xor_sync(0xffffffffu, tvmin, o));
    if (lane == 0) sm_min[warp] = tvmin;
    __syncthreads();
    if (tid == 0) {
        unsigned mn = sm_min[0];
        #pragma unroll
        for (int i = 1; i < 8; i++) mn = min(mn, sm_min[i]);
        tileminf[bi * 64 + bj] = (float)mn;
    }
}

// ---------------------------------------------------------------------------
__device__ __forceinline__ void decode_tile(int xx, int& mat, int& bi, int& bj, bool& diag) {
    if (xx < NTILES_XY) { mat = 0; bi = xx >> 6; bj = xx & 63; diag = false; return; }
    int idx = xx - NTILES_XY; mat = 1;
    if (idx >= NTILES_SYM) { idx -= NTILES_SYM; mat = 2; }
    int b = 0;
    while (idx >= 64 - b) { idx -= 64 - b; b++; }
    bi = b; bj = b + idx; diag = (bi == bj);
}

struct TA {
    const unsigned short* C[3];
    const float* tmin[3];
    const float* gr[3];
    const float* gc[3];
    float2* Pr[3];
    float2* Pc[3];
    int rslot[3], cslot[3];
};

// ---------------------------------------------------------------------------
// Mode A (eps >= 1): factored exponential, per-tile anchor, 1 ex2/element.
// ---------------------------------------------------------------------------
__global__ void __launch_bounds__(256)
tile_softmin_A(TA ta, float k1, float kb, int slot) {
    int mat, bi, bj; bool diag;
    decode_tile(blockIdx.x, mat, bi, bj, diag);
    const int i0 = bi * 128, j0 = bj * 128;
    const unsigned short* __restrict__ C = ta.C[mat];

    __shared__ float Rj[128], Si[128];
    __shared__ float partR[128][17];
    __shared__ float partC[128][17];

    const int tid = threadIdx.x;
    const int lane = tid & 31, warp = tid >> 5;
    const int wy = warp >> 1, wx = warp & 1;
    const int ty2 = lane & 3, tx2 = lane >> 2;
    const int r0 = wy * 32 + ty2 * 8;
    const int c0 = wx * 64 + tx2 * 8;
    const int segR = wx * 8 + tx2;
    const int segC = wy * 4 + ty2;

    const float gmr = dec_f(d_stat_max[slot * 4 + ta.rslot[mat]]);
    const float gmc = dec_f(d_stat_max[slot * 4 + ta.cslot[mat]]);
    const float tminq = ta.tmin[mat][bi * 64 + bj];

    if (tid < 128) {
        Rj[tid] = ex2_fast((ta.gr[mat][j0 + tid] - gmr) * k1);
        Si[tid] = ex2_fast((ta.gc[mat][i0 + tid] - gmc) * k1);
    }
    __syncthreads();

    uint4 w[8];
    #pragma unroll
    for (int p = 0; p < 8; p++)
        w[p] = *(const uint4*)(C + (size_t)(i0 + r0 + p) * NPTS + j0 + c0);

    const float kq  = -k1 * QINV;
    const float c0f = -tminq * kq;

    float rj[8];
    #pragma unroll
    for (int q = 0; q < 8; q++) rj[q] = Rj[c0 + q];
    float cs[8];
    #pragma unroll
    for (int q = 0; q < 8; q++) cs[q] = 0.0f;

    #pragma unroll
    for (int p = 0; p < 8; p++) {
        float sp = Si[r0 + p];
        uint4 wq = w[p];
        float e0 = ex2_fast(fmaf(dec_lo(wq.x), kq, c0f));
        float e1 = ex2_fast(fmaf(dec_hi(wq.x), kq, c0f));
        float e2 = ex2_fast(fmaf(dec_lo(wq.y), kq, c0f));
        float e3 = ex2_fast(fmaf(dec_hi(wq.y), kq, c0f));
        float e4 = ex2_fast(fmaf(dec_lo(wq.z), kq, c0f));
        float e5 = ex2_fast(fmaf(dec_hi(wq.z), kq, c0f));
        float e6 = ex2_fast(fmaf(dec_lo(wq.w), kq, c0f));
        float e7 = ex2_fast(fmaf(dec_hi(wq.w), kq, c0f));
        partR[r0 + p][segR] = e0 * rj[0] + e1 * rj[1] + e2 * rj[2] + e3 * rj[3]
                            + e4 * rj[4] + e5 * rj[5] + e6 * rj[6] + e7 * rj[7];
        cs[0] = fmaf(e0, sp, cs[0]); cs[1] = fmaf(e1, sp, cs[1]);
        cs[2] = fmaf(e2, sp, cs[2]); cs[3] = fmaf(e3, sp, cs[3]);
        cs[4] = fmaf(e4, sp, cs[4]); cs[5] = fmaf(e5, sp, cs[5]);
        cs[6] = fmaf(e6, sp, cs[6]); cs[7] = fmaf(e7, sp, cs[7]);
    }
    #pragma unroll
    for (int q = 0; q < 8; q++) partC[c0 + q][segC] = cs[q];
    __syncthreads();

    const float A_r = fmaf(k1, gmr, kb) + kq * tminq;
    const float A_c = fmaf(k1, gmc, kb) + kq * tminq;
    if (tid < 128) {
        float s = 0.0f;
        #pragma unroll
        for (int k = 0; k < 16; k++) s += partR[tid][k];
        ta.Pr[mat][(size_t)bj * NPTS + i0 + tid] = make_float2(A_r, s);
    } else if (!diag) {
        int j = tid - 128;
        float s = 0.0f;
        #pragma unroll
        for (int k = 0; k < 16; k++) s += partC[j][k];
        ta.Pc[mat][(size_t)bi * NPTS + j0 + j] = make_float2(A_c, s);
    }
}

// ---------------------------------------------------------------------------
// Mode C (eps < 1): exact per-row/per-col anchors (register pass 1),
// then 2 ex2/elem sums (pass 2). Branchless; safe at any eps.
//   t_pq = C_pq*kq + Gr[q]  (row dir, weights over columns j)
//   u_pq = C_pq*kq + Gc[p]  (col dir, weights over rows i)
// ---------------------------------------------------------------------------
__global__ void __launch_bounds__(256)
tile_softmin_C(TA ta, float k1, float kb) {
    int mat, bi, bj; bool diag;
    decode_tile(blockIdx.x, mat, bi, bj, diag);
    const int i0 = bi * 128, j0 = bj * 128;
    const unsigned short* __restrict__ C = ta.C[mat];

    __shared__ float Gr[128], Gc[128];
    __shared__ float partR[128][17];
    __shared__ float partC[128][17];
    __shared__ float Mr[128], Mc[128];

    const int tid = threadIdx.x;
    const int lane = tid & 31, warp = tid >> 5;
    const int wy = warp >> 1, wx = warp & 1;
    const int ty2 = lane & 3, tx2 = lane >> 2;
    const int r0 = wy * 32 + ty2 * 8;
    const int c0 = wx * 64 + tx2 * 8;
    const int segR = wx * 8 + tx2;
    const int segC = wy * 4 + ty2;

    if (tid < 128) {
        Gr[tid] = fmaf(ta.gr[mat][j0 + tid], k1, kb);
        Gc[tid] = fmaf(ta.gc[mat][i0 + tid], k1, kb);
    }
    __syncthreads();

    uint4 w[8];
    #pragma unroll
    for (int p = 0; p < 8; p++)
        w[p] = *(const uint4*)(C + (size_t)(i0 + r0 + p) * NPTS + j0 + c0);

    const float kq = -k1 * QINV;
    float G[8];
    #pragma unroll
    for (int q = 0; q < 8; q++) G[q] = Gr[c0 + q];

    // ---- pass 1: exact row/col maxes ----
    float cmx[8];
    #pragma unroll
    for (int q = 0; q < 8; q++) cmx[q] = -1e30f;
    #pragma unroll
    for (int p = 0; p < 8; p++) {
        uint4 wq = w[p];
        float b0 = dec_lo(wq.x) * kq, b1 = dec_hi(wq.x) * kq;
        float b2 = dec_lo(wq.y) * kq, b3 = dec_hi(wq.y) * kq;
        float b4 = dec_lo(wq.z) * kq, b5 = dec_hi(wq.z) * kq;
        float b6 = dec_lo(wq.w) * kq, b7 = dec_hi(wq.w) * kq;
        float rm = fmaxf(fmaxf(fmaxf(b0 + G[0], b1 + G[1]), fmaxf(b2 + G[2], b3 + G[3])),
                         fmaxf(fmaxf(b4 + G[4], b5 + G[5]), fmaxf(b6 + G[6], b7 + G[7])));
        partR[r0 + p][segR] = rm;
        // col dir shares base b; Gc[p] added at combine time (same for all q of this p)
        cmx[0] = fmaxf(cmx[0], b0 + Gc[r0 + p]); cmx[1] = fmaxf(cmx[1], b1 + Gc[r0 + p]);
        cmx[2] = fmaxf(cmx[2], b2 + Gc[r0 + p]); cmx[3] = fmaxf(cmx[3], b3 + Gc[r0 + p]);
        cmx[4] = fmaxf(cmx[4], b4 + Gc[r0 + p]); cmx[5] = fmaxf(cmx[5], b5 + Gc[r0 + p]);
        cmx[6] = fmaxf(cmx[6], b6 + Gc[r0 + p]); cmx[7] = fmaxf(cmx[7], b7 + Gc[r0 + p]);
    }
    #pragma unroll
    for (int q = 0; q < 8; q++) partC[c0 + q][segC] = cmx[q];
    __syncthreads();

    if (tid < 128) {
        float M = partR[tid][0];
        #pragma unroll
        for (int k = 1; k < 16; k++) M = fmaxf(M, partR[tid][k]);
        Mr[tid] = M;
    } else {
        int j = tid - 128;
        float M = partC[j][0];
        #pragma unroll
        for (int k = 1; k < 16; k++) M = fmaxf(M, partC[j][k]);
        Mc[j] = M;
    }
    __syncthreads();

    // ---- pass 2: anchored sums ----
    float mrl[8], mcl[8], gcl[8];
    #pragma unroll
    for (int p = 0; p < 8; p++) { mrl[p] = Mr[r0 + p]; gcl[p] = Gc[r0 + p]; }
    #pragma unroll
    for (int q = 0; q < 8; q++) mcl[q] = Mc[c0 + q];

    float cs[8];
    #pragma unroll
    for (int q = 0; q < 8; q++) cs[q] = 0.0f;

    #pragma unroll
    for (int p = 0; p < 8; p++) {
        uint4 wq = w[p];
        float b0 = dec_lo(wq.x) * kq, b1 = dec_hi(wq.x) * kq;
        float b2 = dec_lo(wq.y) * kq, b3 = dec_hi(wq.y) * kq;
        float b4 = dec_lo(wq.z) * kq, b5 = dec_hi(wq.z) * kq;
        float b6 = dec_lo(wq.w) * kq, b7 = dec_hi(wq.w) * kq;
        float mr = mrl[p], gc = gcl[p];
        float rs = ex2_fast(b0 + G[0] - mr) + ex2_fast(b1 + G[1] - mr)
                 + ex2_fast(b2 + G[2] - mr) + ex2_fast(b3 + G[3] - mr)
                 + ex2_fast(b4 + G[4] - mr) + ex2_fast(b5 + G[5] - mr)
                 + ex2_fast(b6 + G[6] - mr) + ex2_fast(b7 + G[7] - mr);
        partR[r0 + p][segR] = rs;
        cs[0] += ex2_fast(b0 + gc - mcl[0]); cs[1] += ex2_fast(b1 + gc - mcl[1]);
        cs[2] += ex2_fast(b2 + gc - mcl[2]); cs[3] += ex2_fast(b3 + gc - mcl[3]);
        cs[4] += ex2_fast(b4 + gc - mcl[4]); cs[5] += ex2_fast(b5 + gc - mcl[5]);
        cs[6] += ex2_fast(b6 + gc - mcl[6]); cs[7] += ex2_fast(b7 + gc - mcl[7]);
    }
    #pragma unroll
    for (int q = 0; q < 8; q++) partC[c0 + q][segC] = cs[q];
    __syncthreads();

    if (tid < 128) {
        float s = 0.0f;
        #pragma unroll
        for (int k = 0; k < 16; k++) s += partR[tid][k];
        ta.Pr[mat][(size_t)bj * NPTS + i0 + tid] = make_float2(Mr[tid], s);
    } else if (!diag) {
        int j = tid - 128;
        float s = 0.0f;
        #pragma unroll
        for (int k = 0; k < 16; k++) s += partC[j][k];
        ta.Pc[mat][(size_t)bi * NPTS + j0 + j] = make_float2(Mc[j], s);
    }
}

// ---------------------------------------------------------------------------
// Stage 2: combine 64 (anchor,sum) partials per row; per-slot max stats.
// ---------------------------------------------------------------------------
struct S2 {
    const float2* P[4];
    float* g[4];
    int gslot[4];
};

__global__ void __launch_bounds__(128)
stage2_all(S2 s2, float eps, int avg, int slot) {
    const int a = blockIdx.y;
    const int lane = threadIdx.x & 31;
    const int part = threadIdx.x >> 5;
    const int r = blockIdx.x * 32 + lane;
    const float2* __restrict__ P = s2.P[a] + (size_t)part * 16 * NPTS + r;

    float2 p[16];
    #pragma unroll
    for (int k = 0; k < 16; k++) p[k] = P[(size_t)k * NPTS];
    float M = p[0].x;
    #pragma unroll
    for (int k = 1; k < 16; k++) M = fmaxf(M, p[k].x);
    float S = 0.0f;
    #pragma unroll
    for (int k = 0; k < 16; k++) S = fmaf(p[k].y, ex2_fast(p[k].x - M), S);

    __shared__ float sm_m[4][33], sm_s[4][33];
    sm_m[part][lane] = M;
    sm_s[part][lane] = S;
    __syncthreads();

    if (threadIdx.x < 32) {
        float m0 = sm_m[0][lane], m1 = sm_m[1][lane];
        float m2 = sm_m[2][lane], m3 = sm_m[3][lane];
        float Mx = fmaxf(fmaxf(m0, m1), fmaxf(m2, m3));
        float Sx = sm_s[0][lane] * ex2_fast(m0 - Mx)
                 + sm_s[1][lane] * ex2_fast(m1 - Mx)
                 + sm_s[2][lane] * ex2_fast(m2 - Mx)
                 + sm_s[3][lane] * ex2_fast(m3 - Mx);
        float val = -eps * LN2_F * (Mx + lg2_fast(Sx));
        if (avg) val = 0.5f * (s2.g[a][r] + val);
        s2.g[a][r] = val;

        float vmx = val;
        #pragma unroll
        for (int o = 16; o > 0; o >>= 1)
            vmx = fmaxf(vmx, __shfl_xor_sync(0xffffffffu, vmx, o));
        if (lane == 0)
            atomicMax(&d_stat_max[slot * 4 + s2.gslot[a]], enc_f(vmx));
    }
}

// ---------------------------------------------------------------------------
__global__ void final_kernel(const float* __restrict__ fbf, const float* __restrict__ faf,
                             const float* __restrict__ gaf, const float* __restrict__ gbf,
                             float* __restrict__ out) {
    __shared__ float sh[256];
    float s = 0.0f;
    for (int i = threadIdx.x; i < NPTS; i += 256)
        s += (fbf[i] - faf[i]) + (gaf[i] - gbf[i]);
    sh[threadIdx.x] = s;
    __syncthreads();
    #pragma unroll
    for (int o = 128; o > 0; o >>= 1) {
        if (threadIdx.x < o) sh[threadIdx.x] += sh[threadIdx.x + o];
        __syncthreads();
    }
    if (threadIdx.x == 0) out[0] = sh[0] * (1.0f / (float)NPTS);
}

// ---------------------------------------------------------------------------
extern "C" void kernel_launch(void* const* d_in, const int* in_sizes, int n_in,
                              void* d_out, int out_size) {
    (void)in_sizes; (void)n_in; (void)out_size;
    const float* x = (const float*)d_in[0];
    const float* y = (const float*)d_in[1];
    float* out = (float*)d_out;

    unsigned short* cq = nullptr;
    float2* part = nullptr;
    float *vec = nullptr, *tmin = nullptr;
    cudaGetSymbolAddress((void**)&cq,   d_cq);
    cudaGetSymbolAddress((void**)&part, d_part);
    cudaGetSymbolAddress((void**)&vec,  d_vecbuf);
    cudaGetSymbolAddress((void**)&tmin, d_tilemin);

    unsigned short* Cxy = cq;
    unsigned short* Cxx = cq + NN;
    unsigned short* Cyy = cq + 2 * NN;
    float2* Pft = part;
    float2* Pgt = part + (size_t)NCHUNK * NPTS;
    float2* Pfs = part + 2 * (size_t)NCHUNK * NPTS;
    float2* Pgs = part + 3 * (size_t)NCHUNK * NPTS;

    float* hx   = vec + (size_t)V_HX   * NPTS;
    float* hy   = vec + (size_t)V_HY   * NPTS;
    float* zero = vec + (size_t)V_ZERO * NPTS;
    float* faa  = vec + (size_t)V_FAA  * NPTS;
    float* gbb  = vec + (size_t)V_GBB  * NPTS;
    float* gab  = vec + (size_t)V_GAB  * NPTS;
    float* fba  = vec + (size_t)V_FBA  * NPTS;
    float* ft   = vec + (size_t)V_FT   * NPTS;
    float* gt   = vec + (size_t)V_GT   * NPTS;
    float* fs   = vec + (size_t)V_FS   * NPTS;
    float* gs   = vec + (size_t)V_GS   * NPTS;

    static const float EPS[11] = {1024.0f, 256.0f, 64.0f, 16.0f, 4.0f, 1.0f,
                                  0.25f, 0.0625f, 0.015625f, 0.00390625f, 0.0025f};

    init_misc_kernel<<<1, 256>>>();
    prep_kernel<<<2048, 256>>>(x, y, hx, hy);
    gemm_cost_q<<<dim3(64, 64, 3), 256>>>(x, y, hx, hy, cq, tmin);

    TA init_ta, ta;
    init_ta.C[0] = Cxy; init_ta.C[1] = Cxx; init_ta.C[2] = Cyy;
    init_ta.tmin[0] = tmin; init_ta.tmin[1] = tmin + 4096; init_ta.tmin[2] = tmin + 8192;
    init_ta.Pr[0] = Pft; init_ta.Pc[0] = Pgt;
    init_ta.Pr[1] = Pfs; init_ta.Pc[1] = Pfs;
    init_ta.Pr[2] = Pgs; init_ta.Pc[2] = Pgs;
    init_ta.rslot[0] = 0; init_ta.cslot[0] = 1;
    init_ta.rslot[1] = 2; init_ta.cslot[1] = 2;
    init_ta.rslot[2] = 3; init_ta.cslot[2] = 3;
    for (int m = 0; m < 3; m++) { init_ta.gr[m] = zero; init_ta.gc[m] = zero; }
    ta = init_ta;
    ta.gr[0] = gab; ta.gc[0] = fba;
    ta.gr[1] = faa; ta.gc[1] = faa;
    ta.gr[2] = gbb; ta.gc[2] = gbb;

    S2 s2_loop, s2_fin;
    s2_loop.P[0] = Pft; s2_loop.P[1] = Pgt; s2_loop.P[2] = Pfs; s2_loop.P[3] = Pgs;
    s2_loop.g[0] = fba; s2_loop.g[1] = gab; s2_loop.g[2] = faa; s2_loop.g[3] = gbb;
    s2_loop.gslot[0] = 1; s2_loop.gslot[1] = 0; s2_loop.gslot[2] = 2; s2_loop.gslot[3] = 3;
    s2_fin = s2_loop;
    s2_fin.g[0] = ft; s2_fin.g[1] = gt; s2_fin.g[2] = fs; s2_fin.g[3] = gs;

    dim3 s2g(256, 4);
    const float KB = KB_CONST;

    {   // init round: eps0 = 1024, g = 0 (stats slot 0 = enc(0))
        float e0 = EPS[0];
        tile_softmin_A<<<NTILES_ALL, 256>>>(init_ta, LOG2E_F / e0, KB, 0);
        stage2_all<<<s2g, 128>>>(s2_loop, e0, 0, 1);
    }

    for (int it = 0; it < 11; it++) {
        float e = EPS[it];
        float k1 = LOG2E_F / e;
        int cslot = it + 1, pslot = it + 2;
        if (e >= 1.0f)
            tile_softmin_A<<<NTILES_ALL, 256>>>(ta, k1, KB, cslot);
        else
            tile_softmin_C<<<NTILES_ALL, 256>>>(ta, k1, KB);
        stage2_all<<<s2g, 128>>>(s2_loop, e, 1, pslot);
    }

    {   // final non-averaged extrapolation at eps = blur^p
        float ef = EPS[10];
        tile_softmin_C<<<NTILES_ALL, 256>>>(ta, LOG2E_F / ef, KB);
        stage2_all<<<s2g, 128>>>(s2_fin, ef, 0, 13);
    }

    final_kernel<<<1, 256>>>(ft, fs, gt, gs, out);
}

// round 16
// speedup vs baseline: 1.1774x; 1.1774x over previous
#include <cuda_runtime.h>
#include <cstddef>

// ---------------------------------------------------------------------------
// Sinkhorn divergence (geomloss p=2, blur=0.05, scaling=0.5, diameter=32)
// N = M = 8192, D = 64.  R16 = R14 with:
//  (1) drift gate removed from sparse path (lists collected with current
//      potentials; post-collection drift provably too small to matter),
//  (2) a sparse probe inserted at ncu capture slot #6 (steady-state lists)
//      to finally measure the list path. Probe outputs are overwritten
//      before use -> correctness-neutral and deterministic.
// ---------------------------------------------------------------------------

#define NPTS 8192
#define DIMS 64
#define NN      ((size_t)NPTS * (size_t)NPTS)
#define NCHUNK  64
#define QSCALE  128.0f
#define QINV    (1.0f / 128.0f)
#define NTILES_XY  4096
#define NTILES_SYM 2080
#define NTILES_ALL (NTILES_XY + 2 * NTILES_SYM)

#define LOG2E_F 1.4426950408889634f
#define LN2_F   0.6931471805599453f
#define NEG_LOG_N_F (-9.010913347279288f)   // -ln(8192)
#define KB_CONST (NEG_LOG_N_F * LOG2E_F)
#define SKIP_BITS 30.0f

// sparse machinery
#define KCAP 512
#define T_UNITS 12.0f
#define NSLOTS 14

__device__ __align__(256) unsigned short d_cq[3 * NN];               // 384 MB
__device__ __align__(256) float2 d_part[4 * (size_t)NCHUNK * NPTS];  // 16 MB
__device__ __align__(256) float  d_tilemin[3 * 4096];
__device__ __align__(256) float  d_vecbuf[11 * NPTS];
__device__ __align__(256) unsigned d_list[4 * (size_t)NPTS * KCAP];  // 64 MB
__device__ __align__(256) unsigned d_cnt[4 * NPTS];
__device__ __align__(256) float  d_score[4 * NPTS];
__device__ __align__(256) unsigned d_stat_max[NSLOTS * 4];

#define V_HX 0
#define V_HY 1
#define V_ZERO 2
#define V_FAA 3
#define V_GBB 4
#define V_GAB 5
#define V_FBA 6
#define V_FT 7
#define V_GT 8
#define V_FS 9
#define V_GS 10

__device__ __forceinline__ float ex2_fast(float x) {
    float r; asm("ex2.approx.ftz.f32 %0, %1;" : "=f"(r) : "f"(x)); return r;
}
__device__ __forceinline__ float lg2_fast(float x) {
    float r; asm("lg2.approx.f32 %0, %1;" : "=f"(r) : "f"(x)); return r;
}
__device__ __forceinline__ float dec_lo(unsigned w) {
    return __uint_as_float(__byte_perm(w, 0x4B000000u, 0x7410)) - 8388608.0f;
}
__device__ __forceinline__ float dec_hi(unsigned w) {
    return __uint_as_float(__byte_perm(w, 0x4B000000u, 0x7432)) - 8388608.0f;
}
__device__ __forceinline__ unsigned enc_f(float f) {
    unsigned u = __float_as_uint(f);
    return (u & 0x80000000u) ? ~u : (u | 0x80000000u);
}
__device__ __forceinline__ float dec_f(unsigned u) {
    return __uint_as_float((u & 0x80000000u) ? (u ^ 0x80000000u) : ~u);
}

// ---------------------------------------------------------------------------
__global__ void init_misc_kernel() {
    int idx = blockIdx.x * 256 + threadIdx.x;
    if (idx < 4 * NPTS) d_cnt[idx] = 0u;
    if (idx < NSLOTS * 4) d_stat_max[idx] = enc_f(-3e38f);
    if (idx < 4) d_stat_max[idx] = enc_f(0.0f);   // slot 0: zero potentials
}

__global__ void prep_kernel(const float* __restrict__ x, const float* __restrict__ y,
                            float* __restrict__ hx, float* __restrict__ hy) {
    int gw = (blockIdx.x * blockDim.x + threadIdx.x) >> 5;
    int lane = threadIdx.x & 31;
    const float* X = (gw < NPTS) ? x : y;
    float* H = (gw < NPTS) ? hx : hy;
    int row = (gw < NPTS) ? gw : gw - NPTS;
    float v0 = X[(size_t)row * DIMS + lane];
    float v1 = X[(size_t)row * DIMS + 32 + lane];
    float s = v0 * v0 + v1 * v1;
    #pragma unroll
    for (int o = 16; o > 0; o >>= 1) s += __shfl_xor_sync(0xffffffffu, s, o);
    if (lane == 0) H[row] = 0.5f * s;
}

// ---------------------------------------------------------------------------
// merged GEMM: z=0 Cxy, z=1 Cxx upper, z=2 Cyy upper; u16 quant + tile min.
// ---------------------------------------------------------------------------
__global__ void __launch_bounds__(256)
gemm_cost_q(const float* __restrict__ x, const float* __restrict__ y,
            const float* __restrict__ hx, const float* __restrict__ hy,
            unsigned short* __restrict__ cq, float* __restrict__ tmin) {
    const int mz = blockIdx.z;
    int bi = blockIdx.y, bj = blockIdx.x;
    if (mz > 0 && bi > bj) return;
    const float* A  = (mz == 2) ? y : x;
    const float* B  = (mz == 0 || mz == 2) ? y : x;
    const float* ha = (mz == 2) ? hy : hx;
    const float* hb = (mz == 0 || mz == 2) ? hy : hx;
    unsigned short* C = cq + (size_t)mz * NN;
    float* tileminf = tmin + mz * 4096;

    const int i0 = bi * 128, j0 = bj * 128;
    __shared__ float As[32][132];
    __shared__ float Bs[32][132];
    __shared__ unsigned sm_min[8];

    const int tid = threadIdx.x;
    const int lane = tid & 31, warp = tid >> 5;
    const int wy = warp >> 1, wx = warp & 1;
    const int ty2 = lane & 3, tx2 = lane >> 2;
    const int r0 = wy * 32 + ty2 * 8;
    const int c0 = wx * 64 + tx2 * 8;

    float acc[8][8];
    #pragma unroll
    for (int p = 0; p < 8; p++)
        #pragma unroll
        for (int q = 0; q < 8; q++) acc[p][q] = 0.0f;

    #pragma unroll
    for (int kc = 0; kc < 2; kc++) {
        #pragma unroll
        for (int u = 0; u < 4; u++) {
            int idx = tid + 256 * u;
            int row = idx >> 3, kq = idx & 7;
            float4 av = *(const float4*)(A + (size_t)(i0 + row) * DIMS + kc * 32 + kq * 4);
            float4 bv = *(const float4*)(B + (size_t)(j0 + row) * DIMS + kc * 32 + kq * 4);
            As[kq * 4 + 0][row] = av.x; As[kq * 4 + 1][row] = av.y;
            As[kq * 4 + 2][row] = av.z; As[kq * 4 + 3][row] = av.w;
            Bs[kq * 4 + 0][row] = bv.x; Bs[kq * 4 + 1][row] = bv.y;
            Bs[kq * 4 + 2][row] = bv.z; Bs[kq * 4 + 3][row] = bv.w;
        }
        __syncthreads();
        #pragma unroll 4
        for (int k = 0; k < 32; k++) {
            float a[8], b[8];
            *(float4*)&a[0] = *(const float4*)&As[k][r0];
            *(float4*)&a[4] = *(const float4*)&As[k][r0 + 4];
            *(float4*)&b[0] = *(const float4*)&Bs[k][c0];
            *(float4*)&b[4] = *(const float4*)&Bs[k][c0 + 4];
            #pragma unroll
            for (int p = 0; p < 8; p++)
                #pragma unroll
                for (int q = 0; q < 8; q++)
                    acc[p][q] = fmaf(a[p], b[q], acc[p][q]);
        }
        __syncthreads();
    }

    float hav[8], hbv[8];
    #pragma unroll
    for (int p = 0; p < 8; p++) hav[p] = ha[i0 + r0 + p];
    #pragma unroll
    for (int q = 0; q < 8; q++) hbv[q] = hb[j0 + c0 + q];

    unsigned tvmin = 0xFFFFu;
    #pragma unroll
    for (int p = 0; p < 8; p++) {
        unsigned v[8];
        #pragma unroll
        for (int q = 0; q < 8; q++) {
            float val = fmaxf(hav[p] + hbv[q] - acc[p][q], 0.0f) * QSCALE;
            unsigned xq = __float2uint_rn(val);
            v[q] = xq > 65535u ? 65535u : xq;
            tvmin = min(tvmin, v[q]);
        }
        uint4 w;
        w.x = v[0] | (v[1] << 16); w.y = v[2] | (v[3] << 16);
        w.z = v[4] | (v[5] << 16); w.w = v[6] | (v[7] << 16);
        *(uint4*)(C + (size_t)(i0 + r0 + p) * NPTS + j0 + c0) = w;
    }
    #pragma unroll
    for (int o = 16; o > 0; o >>= 1)
        tvmin = min(tvmin, __shfl_xor_sync(0xffffffffu, tvmin, o));
    if (lane == 0) sm_min[warp] = tvmin;
    __syncthreads();
    if (tid == 0) {
        unsigned mn = sm_min[0];
        #pragma unroll
        for (int i = 1; i < 8; i++) mn = min(mn, sm_min[i]);
        tileminf[bi * 64 + bj] = (float)mn;
    }
}

// ---------------------------------------------------------------------------
__device__ __forceinline__ void decode_tile(int xx, int& mat, int& bi, int& bj, bool& diag) {
    if (xx < NTILES_XY) { mat = 0; bi = xx >> 6; bj = xx & 63; diag = false; return; }
    int idx = xx - NTILES_XY; mat = 1;
    if (idx >= NTILES_SYM) { idx -= NTILES_SYM; mat = 2; }
    int b = 0;
    while (idx >= 64 - b) { idx -= 64 - b; b++; }
    bi = b; bj = b + idx; diag = (bi == bj);
}

struct TA {
    const unsigned short* C[3];
    const float* tmin[3];
    const float* gr[3];
    const float* gc[3];
    float2* Pr[3];
    float2* Pc[3];
    int rslot[3], cslot[3];
};

// ---------------------------------------------------------------------------
// Mode A (eps >= 1): factored exponential, per-tile anchor, 1 ex2/element.
// ---------------------------------------------------------------------------
__global__ void __launch_bounds__(256)
tile_softmin_A(TA ta, float k1, float kb, int slot) {
    int mat, bi, bj; bool diag;
    decode_tile(blockIdx.x, mat, bi, bj, diag);
    const int i0 = bi * 128, j0 = bj * 128;
    const unsigned short* __restrict__ C = ta.C[mat];

    __shared__ float Rj[128], Si[128];
    __shared__ float partR[128][17];
    __shared__ float partC[128][17];

    const int tid = threadIdx.x;
    const int lane = tid & 31, warp = tid >> 5;
    const int wy = warp >> 1, wx = warp & 1;
    const int ty2 = lane & 3, tx2 = lane >> 2;
    const int r0 = wy * 32 + ty2 * 8;
    const int c0 = wx * 64 + tx2 * 8;
    const int segR = wx * 8 + tx2;
    const int segC = wy * 4 + ty2;

    const float gmr = dec_f(d_stat_max[slot * 4 + ta.rslot[mat]]);
    const float gmc = dec_f(d_stat_max[slot * 4 + ta.cslot[mat]]);
    const float tminq = ta.tmin[mat][bi * 64 + bj];

    if (tid < 128) {
        Rj[tid] = ex2_fast((ta.gr[mat][j0 + tid] - gmr) * k1);
        Si[tid] = ex2_fast((ta.gc[mat][i0 + tid] - gmc) * k1);
    }
    __syncthreads();

    uint4 w[8];
    #pragma unroll
    for (int p = 0; p < 8; p++)
        w[p] = *(const uint4*)(C + (size_t)(i0 + r0 + p) * NPTS + j0 + c0);

    const float kq  = -k1 * QINV;
    const float c0f = -tminq * kq;

    float rj[8];
    #pragma unroll
    for (int q = 0; q < 8; q++) rj[q] = Rj[c0 + q];
    float cs[8];
    #pragma unroll
    for (int q = 0; q < 8; q++) cs[q] = 0.0f;

    #pragma unroll
    for (int p = 0; p < 8; p++) {
        float sp = Si[r0 + p];
        uint4 wq = w[p];
        float e0 = ex2_fast(fmaf(dec_lo(wq.x), kq, c0f));
        float e1 = ex2_fast(fmaf(dec_hi(wq.x), kq, c0f));
        float e2 = ex2_fast(fmaf(dec_lo(wq.y), kq, c0f));
        float e3 = ex2_fast(fmaf(dec_hi(wq.y), kq, c0f));
        float e4 = ex2_fast(fmaf(dec_lo(wq.z), kq, c0f));
        float e5 = ex2_fast(fmaf(dec_hi(wq.z), kq, c0f));
        float e6 = ex2_fast(fmaf(dec_lo(wq.w), kq, c0f));
        float e7 = ex2_fast(fmaf(dec_hi(wq.w), kq, c0f));
        partR[r0 + p][segR] = e0 * rj[0] + e1 * rj[1] + e2 * rj[2] + e3 * rj[3]
                            + e4 * rj[4] + e5 * rj[5] + e6 * rj[6] + e7 * rj[7];
        cs[0] = fmaf(e0, sp, cs[0]); cs[1] = fmaf(e1, sp, cs[1]);
        cs[2] = fmaf(e2, sp, cs[2]); cs[3] = fmaf(e3, sp, cs[3]);
        cs[4] = fmaf(e4, sp, cs[4]); cs[5] = fmaf(e5, sp, cs[5]);
        cs[6] = fmaf(e6, sp, cs[6]); cs[7] = fmaf(e7, sp, cs[7]);
    }
    #pragma unroll
    for (int q = 0; q < 8; q++) partC[c0 + q][segC] = cs[q];
    __syncthreads();

    const float A_r = fmaf(k1, gmr, kb) + kq * tminq;
    const float A_c = fmaf(k1, gmc, kb) + kq * tminq;
    if (tid < 128) {
        float s = 0.0f;
        #pragma unroll
        for (int k = 0; k < 16; k++) s += partR[tid][k];
        ta.Pr[mat][(size_t)bj * NPTS + i0 + tid] = make_float2(A_r, s);
    } else if (!diag) {
        int j = tid - 128;
        float s = 0.0f;
        #pragma unroll
        for (int k = 0; k < 16; k++) s += partC[j][k];
        ta.Pc[mat][(size_t)bi * NPTS + j0 + j] = make_float2(A_c, s);
    }
}

// ---------------------------------------------------------------------------
// Mode B (eps = 0.25 only): anchored group partials + 30-bit col skip.
// ---------------------------------------------------------------------------
__device__ __forceinline__ void ms_upd(float& mq, float& sq, float t) {
    if (t > mq) { sq = fmaf(sq, ex2_fast(mq - t), 1.0f); mq = t; }
    else        { sq += ex2_fast(t - mq); }
}

__global__ void __launch_bounds__(256)
tile_softmin_B(TA ta, float k1, float kb) {
    int mat, bi, bj; bool diag;
    decode_tile(blockIdx.x, mat, bi, bj, diag);
    const int i0 = bi * 128, j0 = bj * 128;
    const unsigned short* __restrict__ C = ta.C[mat];

    __shared__ float Gr[128], Gc[128];
    __shared__ float2 partR[128][17];
    __shared__ float2 partC[128][17];

    const int tid = threadIdx.x;
    const int lane = tid & 31, warp = tid >> 5;
    const int wy = warp >> 1, wx = warp & 1;
    const int ty2 = lane & 3, tx2 = lane >> 2;
    const int r0 = wy * 32 + ty2 * 8;
    const int c0 = wx * 64 + tx2 * 8;
    const int segR = wx * 8 + tx2;
    const int segC = wy * 4 + ty2;

    if (tid < 128) {
        Gr[tid] = fmaf(ta.gr[mat][j0 + tid], k1, kb);
        Gc[tid] = fmaf(ta.gc[mat][i0 + tid], k1, kb);
    }
    __syncthreads();

    uint4 w[8];
    #pragma unroll
    for (int p = 0; p < 8; p++)
        w[p] = *(const uint4*)(C + (size_t)(i0 + r0 + p) * NPTS + j0 + c0);

    const float kq = -k1 * QINV;
    float G[8];
    #pragma unroll
    for (int q = 0; q < 8; q++) G[q] = Gr[c0 + q];

    float mc[8], sc[8];
    #pragma unroll
    for (int q = 0; q < 8; q++) { mc[q] = -1e30f; sc[q] = 0.0f; }

    #pragma unroll
    for (int p = 0; p < 8; p++) {
        uint4 wq = w[p];
        float d0 = dec_lo(wq.x), d1 = dec_hi(wq.x);
        float d2 = dec_lo(wq.y), d3 = dec_hi(wq.y);
        float d4 = dec_lo(wq.z), d5 = dec_hi(wq.z);
        float d6 = dec_lo(wq.w), d7 = dec_hi(wq.w);

        float t0 = fmaf(d0, kq, G[0]), t1 = fmaf(d1, kq, G[1]);
        float t2 = fmaf(d2, kq, G[2]), t3 = fmaf(d3, kq, G[3]);
        float t4 = fmaf(d4, kq, G[4]), t5 = fmaf(d5, kq, G[5]);
        float t6 = fmaf(d6, kq, G[6]), t7 = fmaf(d7, kq, G[7]);
        float mp = fmaxf(fmaxf(fmaxf(t0, t1), fmaxf(t2, t3)),
                         fmaxf(fmaxf(t4, t5), fmaxf(t6, t7)));
        float sp = ex2_fast(t0 - mp) + ex2_fast(t1 - mp)
                 + ex2_fast(t2 - mp) + ex2_fast(t3 - mp)
                 + ex2_fast(t4 - mp) + ex2_fast(t5 - mp)
                 + ex2_fast(t6 - mp) + ex2_fast(t7 - mp);
        partR[r0 + p][segR] = make_float2(mp, sp);

        float gcp = Gc[r0 + p];
        float u0 = fmaf(d0, kq, gcp), u1 = fmaf(d1, kq, gcp);
        float u2 = fmaf(d2, kq, gcp), u3 = fmaf(d3, kq, gcp);
        float u4 = fmaf(d4, kq, gcp), u5 = fmaf(d5, kq, gcp);
        float u6 = fmaf(d6, kq, gcp), u7 = fmaf(d7, kq, gcp);
        float ug = fmaxf(fmaxf(fmaxf(u0, u1), fmaxf(u2, u3)),
                         fmaxf(fmaxf(u4, u5), fmaxf(u6, u7)));
        float mn = fminf(fminf(fminf(mc[0], mc[1]), fminf(mc[2], mc[3])),
                         fminf(fminf(mc[4], mc[5]), fminf(mc[6], mc[7])));
        if (ug > mn - SKIP_BITS) {
            ms_upd(mc[0], sc[0], u0); ms_upd(mc[1], sc[1], u1);
            ms_upd(mc[2], sc[2], u2); ms_upd(mc[3], sc[3], u3);
            ms_upd(mc[4], sc[4], u4); ms_upd(mc[5], sc[5], u5);
            ms_upd(mc[6], sc[6], u6); ms_upd(mc[7], sc[7], u7);
        }
    }
    #pragma unroll
    for (int q = 0; q < 8; q++) partC[c0 + q][segC] = make_float2(mc[q], sc[q]);
    __syncthreads();

    if (tid < 128) {
        float2 pr[16];
        #pragma unroll
        for (int k = 0; k < 16; k++) pr[k] = partR[tid][k];
        float M = pr[0].x;
        #pragma unroll
        for (int k = 1; k < 16; k++) M = fmaxf(M, pr[k].x);
        float S = 0.0f;
        #pragma unroll
        for (int k = 0; k < 16; k++) S = fmaf(pr[k].y, ex2_fast(pr[k].x - M), S);
        ta.Pr[mat][(size_t)bj * NPTS + i0 + tid] = make_float2(M, S);
    } else if (!diag) {
        int j = tid - 128;
        float2 pc[16];
        #pragma unroll
        for (int k = 0; k < 16; k++) pc[k] = partC[j][k];
        float M = pc[0].x;
        #pragma unroll
        for (int k = 1; k < 16; k++) M = fmaxf(M, pc[k].x);
        float S = 0.0f;
        #pragma unroll
        for (int k = 0; k < 16; k++) S = fmaf(pc[k].y, ex2_fast(pc[k].x - M), S);
        ta.Pc[mat][(size_t)bi * NPTS + j0 + j] = make_float2(M, S);
    }
}

// ---------------------------------------------------------------------------
// Stage 2: combine 64 partials/row; optional score capture.
// ---------------------------------------------------------------------------
struct S2 {
    const float2* P[4];
    float* g[4];
    int gslot[4];
};

__global__ void __launch_bounds__(128)
stage2_all(S2 s2, float eps, int avg, int slot, int store_score) {
    const int a = blockIdx.y;
    const int lane = threadIdx.x & 31;
    const int part = threadIdx.x >> 5;
    const int r = blockIdx.x * 32 + lane;
    const float2* __restrict__ P = s2.P[a] + (size_t)part * 16 * NPTS + r;

    float2 p[16];
    #pragma unroll
    for (int k = 0; k < 16; k++) p[k] = P[(size_t)k * NPTS];
    float M = p[0].x;
    #pragma unroll
    for (int k = 1; k < 16; k++) M = fmaxf(M, p[k].x);
    float S = 0.0f;
    #pragma unroll
    for (int k = 0; k < 16; k++) S = fmaf(p[k].y, ex2_fast(p[k].x - M), S);

    __shared__ float sm_m[4][33], sm_s[4][33];
    sm_m[part][lane] = M;
    sm_s[part][lane] = S;
    __syncthreads();

    if (threadIdx.x < 32) {
        float m0 = sm_m[0][lane], m1 = sm_m[1][lane];
        float m2 = sm_m[2][lane], m3 = sm_m[3][lane];
        float Mx = fmaxf(fmaxf(m0, m1), fmaxf(m2, m3));
        float Sx = sm_s[0][lane] * ex2_fast(m0 - Mx)
                 + sm_s[1][lane] * ex2_fast(m1 - Mx)
                 + sm_s[2][lane] * ex2_fast(m2 - Mx)
                 + sm_s[3][lane] * ex2_fast(m3 - Mx);
        float val = -eps * LN2_F * (Mx + lg2_fast(Sx));
        if (avg) val = 0.5f * (s2.g[a][r] + val);
        s2.g[a][r] = val;

        if (store_score)
            d_score[a * NPTS + r] = (Mx - KB_CONST) * eps * LN2_F;

        float vmx = val;
        #pragma unroll
        for (int o = 16; o > 0; o >>= 1)
            vmx = fmaxf(vmx, __shfl_xor_sync(0xffffffffu, vmx, o));
        if (lane == 0)
            atomicMax(&d_stat_max[slot * 4 + s2.gslot[a]], enc_f(vmx));
    }
}

// ---------------------------------------------------------------------------
// collect score-relative candidate lists — integer domain, group early-out.
// ---------------------------------------------------------------------------
#define PUSH(d, row, idx, qcv) do {                                           \
    unsigned pos = atomicAdd(&d_cnt[(d) * NPTS + (row)], 1u);                 \
    if (pos < KCAP)                                                           \
        d_list[((size_t)(d) * NPTS + (row)) * KCAP + pos] =                   \
            ((unsigned)(idx) << 16) | (qcv);                                  \
} while (0)

__global__ void __launch_bounds__(256)
collect_lists(const unsigned short* __restrict__ cq,
              const float* __restrict__ gab, const float* __restrict__ fba,
              const float* __restrict__ faa, const float* __restrict__ gbb) {
    const int mz = blockIdx.z;
    int bi = blockIdx.y, bj = blockIdx.x;
    if (mz > 0 && bi > bj) return;
    const unsigned short* C = cq + (size_t)mz * NN;
    const int i0 = bi * 128, j0 = bj * 128;
    const int dirR = (mz == 0) ? 0 : mz + 1;
    const int dirC = (mz == 0) ? 1 : dirR;
    const bool doCol = (mz == 0) || (bi != bj);
    const float* grow = (mz == 0) ? gab : ((mz == 1) ? faa : gbb);
    const float* gcol = (mz == 0) ? fba : ((mz == 1) ? faa : gbb);

    __shared__ int thrRq[128], thrCq[128], gjq[128], giq[128];
    const int tid = threadIdx.x;
    if (tid < 128) {
        thrRq[tid] = (int)floorf((d_score[dirR * NPTS + i0 + tid] - T_UNITS) * QSCALE);
        thrCq[tid] = (int)floorf((d_score[dirC * NPTS + j0 + tid] - T_UNITS) * QSCALE);
        gjq[tid] = (int)ceilf(grow[j0 + tid] * QSCALE);
        giq[tid] = (int)ceilf(gcol[i0 + tid] * QSCALE);
    }
    __syncthreads();

    const int lane = tid & 31, warp = tid >> 5;
    const int wy = warp >> 1, wx = warp & 1;
    const int ty2 = lane & 3, tx2 = lane >> 2;
    const int r0 = wy * 32 + ty2 * 8;
    const int c0 = wx * 64 + tx2 * 8;

    int g8[8], gqmax8 = -0x7fffffff, thrCmin8 = 0x7fffffff;
    #pragma unroll
    for (int q = 0; q < 8; q++) {
        g8[q] = gjq[c0 + q];
        gqmax8 = max(gqmax8, g8[q]);
        thrCmin8 = min(thrCmin8, thrCq[c0 + q]);
    }
    int thrC8[8];
    #pragma unroll
    for (int q = 0; q < 8; q++) thrC8[q] = thrCq[c0 + q];

    #pragma unroll
    for (int p = 0; p < 8; p++) {
        const int rl = r0 + p;
        uint4 wq = *(const uint4*)(C + (size_t)(i0 + rl) * NPTS + j0 + c0);

        unsigned m01 = __vminu2(wq.x, wq.y);
        unsigned m23 = __vminu2(wq.z, wq.w);
        unsigned mm  = __vminu2(m01, m23);
        int minqc = (int)min(mm & 0xffffu, mm >> 16);

        const int thrRrl = thrRq[rl];
        const int girl   = giq[rl];
        int cap = gqmax8 - thrRrl;
        if (doCol) cap = max(cap, girl - thrCmin8);

        if (minqc <= cap) {
            unsigned qc[8];
            qc[0] = wq.x & 0xffffu; qc[1] = wq.x >> 16;
            qc[2] = wq.y & 0xffffu; qc[3] = wq.y >> 16;
            qc[4] = wq.z & 0xffffu; qc[5] = wq.z >> 16;
            qc[6] = wq.w & 0xffffu; qc[7] = wq.w >> 16;
            #pragma unroll
            for (int q = 0; q < 8; q++) {
                if ((int)qc[q] <= g8[q] - thrRrl)
                    PUSH(dirR, i0 + rl, j0 + c0 + q, qc[q]);
                if (doCol && (int)qc[q] <= girl - thrC8[q])
                    PUSH(dirC, j0 + c0 + q, i0 + rl, qc[q]);
            }
        }
    }
}

// ---------------------------------------------------------------------------
// Sparse softmin over candidate lists (single pass). Dense fallback only on
// KCAP overflow (drift gate removed — see header analysis).
// ---------------------------------------------------------------------------
struct SP {
    const float* gw[4];
    float* out[4];
    const unsigned short* mat[4];
};

__global__ void __launch_bounds__(256)
sparse_softmin(SP sp, float k1, float kb, float eps) {
    const int dir = blockIdx.y;
    const int warp = threadIdx.x >> 5, lane = threadIdx.x & 31;

    const float* __restrict__ g = sp.gw[dir];
    const unsigned* __restrict__ lst = d_list + (size_t)dir * NPTS * KCAP;
    const float kq = -k1 * QINV;

    #pragma unroll
    for (int rr = 0; rr < 4; rr++) {
        const int r = blockIdx.x * 32 + warp * 4 + rr;
        const unsigned c = d_cnt[dir * NPTS + r];
        float m = -1e30f, s = 0.0f;
        if (c <= KCAP) {
            const unsigned* __restrict__ L = lst + (size_t)r * KCAP;
            for (unsigned k = lane; k < c; k += 32) {
                unsigned e = L[k];
                float t = fmaf(g[e >> 16], k1, fmaf((float)(e & 0xffffu), kq, kb));
                ms_upd(m, s, t);
            }
        } else {
            const unsigned short* __restrict__ Cm = sp.mat[dir];
            float m4[4] = {-1e30f, -1e30f, -1e30f, -1e30f};
            float s4[4] = {0.0f, 0.0f, 0.0f, 0.0f};
            int it = 0;
            for (int j = lane; j < NPTS; j += 32, it++) {
                size_t off;
                if (dir == 0)      off = (size_t)r * NPTS + j;
                else if (dir == 1) off = (size_t)j * NPTS + r;
                else               off = (j >= r) ? (size_t)r * NPTS + j
                                                  : (size_t)j * NPTS + r;
                float t = fmaf(g[j], k1, fmaf((float)Cm[off], kq, kb));
                int a = it & 3;
                ms_upd(m4[a], s4[a], t);
            }
            m = m4[0]; s = s4[0];
            #pragma unroll
            for (int a = 1; a < 4; a++) {
                float Mx = fmaxf(m, m4[a]);
                s = s * ex2_fast(m - Mx) + s4[a] * ex2_fast(m4[a] - Mx);
                m = Mx;
            }
        }
        #pragma unroll
        for (int o = 16; o > 0; o >>= 1) {
            float m2 = __shfl_xor_sync(0xffffffffu, m, o);
            float s2 = __shfl_xor_sync(0xffffffffu, s, o);
            float Mx = fmaxf(m, m2);
            s = s * ex2_fast(m - Mx) + s2 * ex2_fast(m2 - Mx);
            m = Mx;
        }
        if (lane == 0)
            sp.out[dir][r] = -eps * LN2_F * (m + lg2_fast(s));
    }
}

// ---------------------------------------------------------------------------
__global__ void __launch_bounds__(256)
update_avg(float* __restrict__ fba, const float* __restrict__ ft,
           float* __restrict__ gab, const float* __restrict__ gt,
           float* __restrict__ faa, const float* __restrict__ fs,
           float* __restrict__ gbb, const float* __restrict__ gs) {
    const int i = blockIdx.x * 256 + threadIdx.x;
    fba[i] = 0.5f * (fba[i] + ft[i]);
    gab[i] = 0.5f * (gab[i] + gt[i]);
    faa[i] = 0.5f * (faa[i] + fs[i]);
    gbb[i] = 0.5f * (gbb[i] + gs[i]);
}

// ---------------------------------------------------------------------------
__global__ void final_kernel(const float* __restrict__ fbf, const float* __restrict__ faf,
                             const float* __restrict__ gaf, const float* __restrict__ gbf,
                             float* __restrict__ out) {
    __shared__ float sh[256];
    float s = 0.0f;
    for (int i = threadIdx.x; i < NPTS; i += 256)
        s += (fbf[i] - faf[i]) + (gaf[i] - gbf[i]);
    sh[threadIdx.x] = s;
    __syncthreads();
    #pragma unroll
    for (int o = 128; o > 0; o >>= 1) {
        if (threadIdx.x < o) sh[threadIdx.x] += sh[threadIdx.x + o];
        __syncthreads();
    }
    if (threadIdx.x == 0) out[0] = sh[0] * (1.0f / (float)NPTS);
}

// ---------------------------------------------------------------------------
extern "C" void kernel_launch(void* const* d_in, const int* in_sizes, int n_in,
                              void* d_out, int out_size) {
    (void)in_sizes; (void)n_in; (void)out_size;
    const float* x = (const float*)d_in[0];
    const float* y = (const float*)d_in[1];
    float* out = (float*)d_out;

    unsigned short* cq = nullptr;
    float2* part = nullptr;
    float *vec = nullptr, *tmin = nullptr;
    cudaGetSymbolAddress((void**)&cq,   d_cq);
    cudaGetSymbolAddress((void**)&part, d_part);
    cudaGetSymbolAddress((void**)&vec,  d_vecbuf);
    cudaGetSymbolAddress((void**)&tmin, d_tilemin);

    unsigned short* Cxy = cq;
    unsigned short* Cxx = cq + NN;
    unsigned short* Cyy = cq + 2 * NN;
    float2* Pft = part;
    float2* Pgt = part + (size_t)NCHUNK * NPTS;
    float2* Pfs = part + 2 * (size_t)NCHUNK * NPTS;
    float2* Pgs = part + 3 * (size_t)NCHUNK * NPTS;

    float* hx   = vec + (size_t)V_HX   * NPTS;
    float* hy   = vec + (size_t)V_HY   * NPTS;
    float* zero = vec + (size_t)V_ZERO * NPTS;
    float* faa  = vec + (size_t)V_FAA  * NPTS;
    float* gbb  = vec + (size_t)V_GBB  * NPTS;
    float* gab  = vec + (size_t)V_GAB  * NPTS;
    float* fba  = vec + (size_t)V_FBA  * NPTS;
    float* ft   = vec + (size_t)V_FT   * NPTS;
    float* gt   = vec + (size_t)V_GT   * NPTS;
    float* fs   = vec + (size_t)V_FS   * NPTS;
    float* gs   = vec + (size_t)V_GS   * NPTS;

    static const float EPS[11] = {1024.0f, 256.0f, 64.0f, 16.0f, 4.0f, 1.0f,
                                  0.25f, 0.0625f, 0.015625f, 0.00390625f, 0.0025f};

    init_misc_kernel<<<128, 256>>>();
    prep_kernel<<<2048, 256>>>(x, y, hx, hy);
    gemm_cost_q<<<dim3(64, 64, 3), 256>>>(x, y, hx, hy, cq, tmin);

    TA init_ta, ta;
    init_ta.C[0] = Cxy; init_ta.C[1] = Cxx; init_ta.C[2] = Cyy;
    init_ta.tmin[0] = tmin; init_ta.tmin[1] = tmin + 4096; init_ta.tmin[2] = tmin + 8192;
    init_ta.Pr[0] = Pft; init_ta.Pc[0] = Pgt;
    init_ta.Pr[1] = Pfs; init_ta.Pc[1] = Pfs;
    init_ta.Pr[2] = Pgs; init_ta.Pc[2] = Pgs;
    init_ta.rslot[0] = 0; init_ta.cslot[0] = 1;
    init_ta.rslot[1] = 2; init_ta.cslot[1] = 2;
    init_ta.rslot[2] = 3; init_ta.cslot[2] = 3;
    for (int m = 0; m < 3; m++) { init_ta.gr[m] = zero; init_ta.gc[m] = zero; }
    ta = init_ta;
    ta.gr[0] = gab; ta.gc[0] = fba;
    ta.gr[1] = faa; ta.gc[1] = faa;
    ta.gr[2] = gbb; ta.gc[2] = gbb;

    S2 s2_loop;
    s2_loop.P[0] = Pft; s2_loop.P[1] = Pgt; s2_loop.P[2] = Pfs; s2_loop.P[3] = Pgs;
    s2_loop.g[0] = fba; s2_loop.g[1] = gab; s2_loop.g[2] = faa; s2_loop.g[3] = gbb;
    s2_loop.gslot[0] = 1; s2_loop.gslot[1] = 0; s2_loop.gslot[2] = 2; s2_loop.gslot[3] = 3;

    SP sp;
    sp.gw[0] = gab; sp.gw[1] = fba; sp.gw[2] = faa; sp.gw[3] = gbb;
    sp.out[0] = ft; sp.out[1] = gt; sp.out[2] = fs; sp.out[3] = gs;
    sp.mat[0] = Cxy; sp.mat[1] = Cxy; sp.mat[2] = Cxx; sp.mat[3] = Cyy;

    dim3 s2g(256, 4);
    dim3 spg(256, 4);
    const float KB = KB_CONST;

    {   // init round: eps0 = 1024, g = 0 (stats slot 0 = enc(0))
        float e0 = EPS[0];
        tile_softmin_A<<<NTILES_ALL, 256>>>(init_ta, LOG2E_F / e0, KB, 0);
        stage2_all<<<s2g, 128>>>(s2_loop, e0, 0, 1, 0);
    }

    // PROBE (ncu capture slot #6): sparse list path at steady state.
    // Writes ft/gt/fs/gs which are overwritten before use — correctness-neutral.
    sparse_softmin<<<spg, 256>>>(sp, LOG2E_F / 0.0025f, KB, 0.0025f);

    for (int it = 0; it < 11; it++) {
        float e = EPS[it];
        float k1 = LOG2E_F / e;
        int cslot = it + 1, pslot = it + 2;
        if (e >= 1.0f) {
            tile_softmin_A<<<NTILES_ALL, 256>>>(ta, k1, KB, cslot);
            stage2_all<<<s2g, 128>>>(s2_loop, e, 1, pslot, 0);
        } else if (e >= 0.25f) {
            tile_softmin_B<<<NTILES_ALL, 256>>>(ta, k1, KB);
            stage2_all<<<s2g, 128>>>(s2_loop, e, 1, pslot, 1);   // capture scores
            collect_lists<<<dim3(64, 64, 3), 256>>>(cq, gab, fba, faa, gbb);
        } else {
            sparse_softmin<<<spg, 256>>>(sp, k1, KB, e);
            update_avg<<<32, 256>>>(fba, ft, gab, gt, faa, fs, gbb, gs);
        }
    }

    {   // final non-averaged extrapolation at eps = blur^p (sparse)
        float ef = EPS[10];
        sparse_softmin<<<spg, 256>>>(sp, LOG2E_F / ef, KB, ef);
    }

    final_kernel<<<1, 256>>>(ft, fs, gt, gs, out);
}

// round 17
// speedup vs baseline: 1.6045x; 1.3628x over previous
#include <cuda_runtime.h>
#include <cstddef>

// ---------------------------------------------------------------------------
// Sinkhorn divergence (geomloss p=2, blur=0.05, scaling=0.5, diameter=32)
// N = M = 8192, D = 64.  R17 = R16 with sparse-list OVERFLOW eliminated:
// T_UNITS 12 -> 10 (mean count ~40/row) and KCAP 512 -> 768 (overflow needs
// 19x mean -> never). A single overflowing dir-1 row forced one warp into an
// 85us strided column walk that gated every sparse launch (straggler theory).
// ---------------------------------------------------------------------------

#define NPTS 8192
#define DIMS 64
#define NN      ((size_t)NPTS * (size_t)NPTS)
#define NCHUNK  64
#define QSCALE  128.0f
#define QINV    (1.0f / 128.0f)
#define NTILES_XY  4096
#define NTILES_SYM 2080
#define NTILES_ALL (NTILES_XY + 2 * NTILES_SYM)

#define LOG2E_F 1.4426950408889634f
#define LN2_F   0.6931471805599453f
#define NEG_LOG_N_F (-9.010913347279288f)   // -ln(8192)
#define KB_CONST (NEG_LOG_N_F * LOG2E_F)
#define SKIP_BITS 30.0f

// sparse machinery
#define KCAP 768
#define T_UNITS 10.0f
#define NSLOTS 14

__device__ __align__(256) unsigned short d_cq[3 * NN];               // 384 MB
__device__ __align__(256) float2 d_part[4 * (size_t)NCHUNK * NPTS];  // 16 MB
__device__ __align__(256) float  d_tilemin[3 * 4096];
__device__ __align__(256) float  d_vecbuf[11 * NPTS];
__device__ __align__(256) unsigned d_list[4 * (size_t)NPTS * KCAP];  // 96 MB
__device__ __align__(256) unsigned d_cnt[4 * NPTS];
__device__ __align__(256) float  d_score[4 * NPTS];
__device__ __align__(256) unsigned d_stat_max[NSLOTS * 4];

#define V_HX 0
#define V_HY 1
#define V_ZERO 2
#define V_FAA 3
#define V_GBB 4
#define V_GAB 5
#define V_FBA 6
#define V_FT 7
#define V_GT 8
#define V_FS 9
#define V_GS 10

__device__ __forceinline__ float ex2_fast(float x) {
    float r; asm("ex2.approx.ftz.f32 %0, %1;" : "=f"(r) : "f"(x)); return r;
}
__device__ __forceinline__ float lg2_fast(float x) {
    float r; asm("lg2.approx.f32 %0, %1;" : "=f"(r) : "f"(x)); return r;
}
__device__ __forceinline__ float dec_lo(unsigned w) {
    return __uint_as_float(__byte_perm(w, 0x4B000000u, 0x7410)) - 8388608.0f;
}
__device__ __forceinline__ float dec_hi(unsigned w) {
    return __uint_as_float(__byte_perm(w, 0x4B000000u, 0x7432)) - 8388608.0f;
}
__device__ __forceinline__ unsigned enc_f(float f) {
    unsigned u = __float_as_uint(f);
    return (u & 0x80000000u) ? ~u : (u | 0x80000000u);
}
__device__ __forceinline__ float dec_f(unsigned u) {
    return __uint_as_float((u & 0x80000000u) ? (u ^ 0x80000000u) : ~u);
}

// ---------------------------------------------------------------------------
__global__ void init_misc_kernel() {
    int idx = blockIdx.x * 256 + threadIdx.x;
    if (idx < 4 * NPTS) d_cnt[idx] = 0u;
    if (idx < NSLOTS * 4) d_stat_max[idx] = enc_f(-3e38f);
    if (idx < 4) d_stat_max[idx] = enc_f(0.0f);   // slot 0: zero potentials
}

__global__ void prep_kernel(const float* __restrict__ x, const float* __restrict__ y,
                            float* __restrict__ hx, float* __restrict__ hy) {
    int gw = (blockIdx.x * blockDim.x + threadIdx.x) >> 5;
    int lane = threadIdx.x & 31;
    const float* X = (gw < NPTS) ? x : y;
    float* H = (gw < NPTS) ? hx : hy;
    int row = (gw < NPTS) ? gw : gw - NPTS;
    float v0 = X[(size_t)row * DIMS + lane];
    float v1 = X[(size_t)row * DIMS + 32 + lane];
    float s = v0 * v0 + v1 * v1;
    #pragma unroll
    for (int o = 16; o > 0; o >>= 1) s += __shfl_xor_sync(0xffffffffu, s, o);
    if (lane == 0) H[row] = 0.5f * s;
}

// ---------------------------------------------------------------------------
// merged GEMM: z=0 Cxy, z=1 Cxx upper, z=2 Cyy upper; u16 quant + tile min.
// ---------------------------------------------------------------------------
__global__ void __launch_bounds__(256)
gemm_cost_q(const float* __restrict__ x, const float* __restrict__ y,
            const float* __restrict__ hx, const float* __restrict__ hy,
            unsigned short* __restrict__ cq, float* __restrict__ tmin) {
    const int mz = blockIdx.z;
    int bi = blockIdx.y, bj = blockIdx.x;
    if (mz > 0 && bi > bj) return;
    const float* A  = (mz == 2) ? y : x;
    const float* B  = (mz == 0 || mz == 2) ? y : x;
    const float* ha = (mz == 2) ? hy : hx;
    const float* hb = (mz == 0 || mz == 2) ? hy : hx;
    unsigned short* C = cq + (size_t)mz * NN;
    float* tileminf = tmin + mz * 4096;

    const int i0 = bi * 128, j0 = bj * 128;
    __shared__ float As[32][132];
    __shared__ float Bs[32][132];
    __shared__ unsigned sm_min[8];

    const int tid = threadIdx.x;
    const int lane = tid & 31, warp = tid >> 5;
    const int wy = warp >> 1, wx = warp & 1;
    const int ty2 = lane & 3, tx2 = lane >> 2;
    const int r0 = wy * 32 + ty2 * 8;
    const int c0 = wx * 64 + tx2 * 8;

    float acc[8][8];
    #pragma unroll
    for (int p = 0; p < 8; p++)
        #pragma unroll
        for (int q = 0; q < 8; q++) acc[p][q] = 0.0f;

    #pragma unroll
    for (int kc = 0; kc < 2; kc++) {
        #pragma unroll
        for (int u = 0; u < 4; u++) {
            int idx = tid + 256 * u;
            int row = idx >> 3, kq = idx & 7;
            float4 av = *(const float4*)(A + (size_t)(i0 + row) * DIMS + kc * 32 + kq * 4);
            float4 bv = *(const float4*)(B + (size_t)(j0 + row) * DIMS + kc * 32 + kq * 4);
            As[kq * 4 + 0][row] = av.x; As[kq * 4 + 1][row] = av.y;
            As[kq * 4 + 2][row] = av.z; As[kq * 4 + 3][row] = av.w;
            Bs[kq * 4 + 0][row] = bv.x; Bs[kq * 4 + 1][row] = bv.y;
            Bs[kq * 4 + 2][row] = bv.z; Bs[kq * 4 + 3][row] = bv.w;
        }
        __syncthreads();
        #pragma unroll 4
        for (int k = 0; k < 32; k++) {
            float a[8], b[8];
            *(float4*)&a[0] = *(const float4*)&As[k][r0];
            *(float4*)&a[4] = *(const float4*)&As[k][r0 + 4];
            *(float4*)&b[0] = *(const float4*)&Bs[k][c0];
            *(float4*)&b[4] = *(const float4*)&Bs[k][c0 + 4];
            #pragma unroll
            for (int p = 0; p < 8; p++)
                #pragma unroll
                for (int q = 0; q < 8; q++)
                    acc[p][q] = fmaf(a[p], b[q], acc[p][q]);
        }
        __syncthreads();
    }

    float hav[8], hbv[8];
    #pragma unroll
    for (int p = 0; p < 8; p++) hav[p] = ha[i0 + r0 + p];
    #pragma unroll
    for (int q = 0; q < 8; q++) hbv[q] = hb[j0 + c0 + q];

    unsigned tvmin = 0xFFFFu;
    #pragma unroll
    for (int p = 0; p < 8; p++) {
        unsigned v[8];
        #pragma unroll
        for (int q = 0; q < 8; q++) {
            float val = fmaxf(hav[p] + hbv[q] - acc[p][q], 0.0f) * QSCALE;
            unsigned xq = __float2uint_rn(val);
            v[q] = xq > 65535u ? 65535u : xq;
            tvmin = min(tvmin, v[q]);
        }
        uint4 w;
        w.x = v[0] | (v[1] << 16); w.y = v[2] | (v[3] << 16);
        w.z = v[4] | (v[5] << 16); w.w = v[6] | (v[7] << 16);
        *(uint4*)(C + (size_t)(i0 + r0 + p) * NPTS + j0 + c0) = w;
    }
    #pragma unroll
    for (int o = 16; o > 0; o >>= 1)
        tvmin = min(tvmin, __shfl_xor_sync(0xffffffffu, tvmin, o));
    if (lane == 0) sm_min[warp] = tvmin;
    __syncthreads();
    if (tid == 0) {
        unsigned mn = sm_min[0];
        #pragma unroll
        for (int i = 1; i < 8; i++) mn = min(mn, sm_min[i]);
        tileminf[bi * 64 + bj] = (float)mn;
    }
}

// ---------------------------------------------------------------------------
__device__ __forceinline__ void decode_tile(int xx, int& mat, int& bi, int& bj, bool& diag) {
    if (xx < NTILES_XY) { mat = 0; bi = xx >> 6; bj = xx & 63; diag = false; return; }
    int idx = xx - NTILES_XY; mat = 1;
    if (idx >= NTILES_SYM) { idx -= NTILES_SYM; mat = 2; }
    int b = 0;
    while (idx >= 64 - b) { idx -= 64 - b; b++; }
    bi = b; bj = b + idx; diag = (bi == bj);
}

struct TA {
    const unsigned short* C[3];
    const float* tmin[3];
    const float* gr[3];
    const float* gc[3];
    float2* Pr[3];
    float2* Pc[3];
    int rslot[3], cslot[3];
};

// ---------------------------------------------------------------------------
// Mode A (eps >= 1): factored exponential, per-tile anchor, 1 ex2/element.
// ---------------------------------------------------------------------------
__global__ void __launch_bounds__(256)
tile_softmin_A(TA ta, float k1, float kb, int slot) {
    int mat, bi, bj; bool diag;
    decode_tile(blockIdx.x, mat, bi, bj, diag);
    const int i0 = bi * 128, j0 = bj * 128;
    const unsigned short* __restrict__ C = ta.C[mat];

    __shared__ float Rj[128], Si[128];
    __shared__ float partR[128][17];
    __shared__ float partC[128][17];

    const int tid = threadIdx.x;
    const int lane = tid & 31, warp = tid >> 5;
    const int wy = warp >> 1, wx = warp & 1;
    const int ty2 = lane & 3, tx2 = lane >> 2;
    const int r0 = wy * 32 + ty2 * 8;
    const int c0 = wx * 64 + tx2 * 8;
    const int segR = wx * 8 + tx2;
    const int segC = wy * 4 + ty2;

    const float gmr = dec_f(d_stat_max[slot * 4 + ta.rslot[mat]]);
    const float gmc = dec_f(d_stat_max[slot * 4 + ta.cslot[mat]]);
    const float tminq = ta.tmin[mat][bi * 64 + bj];

    if (tid < 128) {
        Rj[tid] = ex2_fast((ta.gr[mat][j0 + tid] - gmr) * k1);
        Si[tid] = ex2_fast((ta.gc[mat][i0 + tid] - gmc) * k1);
    }
    __syncthreads();

    uint4 w[8];
    #pragma unroll
    for (int p = 0; p < 8; p++)
        w[p] = *(const uint4*)(C + (size_t)(i0 + r0 + p) * NPTS + j0 + c0);

    const float kq  = -k1 * QINV;
    const float c0f = -tminq * kq;

    float rj[8];
    #pragma unroll
    for (int q = 0; q < 8; q++) rj[q] = Rj[c0 + q];
    float cs[8];
    #pragma unroll
    for (int q = 0; q < 8; q++) cs[q] = 0.0f;

    #pragma unroll
    for (int p = 0; p < 8; p++) {
        float sp = Si[r0 + p];
        uint4 wq = w[p];
        float e0 = ex2_fast(fmaf(dec_lo(wq.x), kq, c0f));
        float e1 = ex2_fast(fmaf(dec_hi(wq.x), kq, c0f));
        float e2 = ex2_fast(fmaf(dec_lo(wq.y), kq, c0f));
        float e3 = ex2_fast(fmaf(dec_hi(wq.y), kq, c0f));
        float e4 = ex2_fast(fmaf(dec_lo(wq.z), kq, c0f));
        float e5 = ex2_fast(fmaf(dec_hi(wq.z), kq, c0f));
        float e6 = ex2_fast(fmaf(dec_lo(wq.w), kq, c0f));
        float e7 = ex2_fast(fmaf(dec_hi(wq.w), kq, c0f));
        partR[r0 + p][segR] = e0 * rj[0] + e1 * rj[1] + e2 * rj[2] + e3 * rj[3]
                            + e4 * rj[4] + e5 * rj[5] + e6 * rj[6] + e7 * rj[7];
        cs[0] = fmaf(e0, sp, cs[0]); cs[1] = fmaf(e1, sp, cs[1]);
        cs[2] = fmaf(e2, sp, cs[2]); cs[3] = fmaf(e3, sp, cs[3]);
        cs[4] = fmaf(e4, sp, cs[4]); cs[5] = fmaf(e5, sp, cs[5]);
        cs[6] = fmaf(e6, sp, cs[6]); cs[7] = fmaf(e7, sp, cs[7]);
    }
    #pragma unroll
    for (int q = 0; q < 8; q++) partC[c0 + q][segC] = cs[q];
    __syncthreads();

    const float A_r = fmaf(k1, gmr, kb) + kq * tminq;
    const float A_c = fmaf(k1, gmc, kb) + kq * tminq;
    if (tid < 128) {
        float s = 0.0f;
        #pragma unroll
        for (int k = 0; k < 16; k++) s += partR[tid][k];
        ta.Pr[mat][(size_t)bj * NPTS + i0 + tid] = make_float2(A_r, s);
    } else if (!diag) {
        int j = tid - 128;
        float s = 0.0f;
        #pragma unroll
        for (int k = 0; k < 16; k++) s += partC[j][k];
        ta.Pc[mat][(size_t)bi * NPTS + j0 + j] = make_float2(A_c, s);
    }
}

// ---------------------------------------------------------------------------
// Mode B (eps = 0.25 only): anchored group partials + 30-bit col skip.
// ---------------------------------------------------------------------------
__device__ __forceinline__ void ms_upd(float& mq, float& sq, float t) {
    if (t > mq) { sq = fmaf(sq, ex2_fast(mq - t), 1.0f); mq = t; }
    else        { sq += ex2_fast(t - mq); }
}

__global__ void __launch_bounds__(256)
tile_softmin_B(TA ta, float k1, float kb) {
    int mat, bi, bj; bool diag;
    decode_tile(blockIdx.x, mat, bi, bj, diag);
    const int i0 = bi * 128, j0 = bj * 128;
    const unsigned short* __restrict__ C = ta.C[mat];

    __shared__ float Gr[128], Gc[128];
    __shared__ float2 partR[128][17];
    __shared__ float2 partC[128][17];

    const int tid = threadIdx.x;
    const int lane = tid & 31, warp = tid >> 5;
    const int wy = warp >> 1, wx = warp & 1;
    const int ty2 = lane & 3, tx2 = lane >> 2;
    const int r0 = wy * 32 + ty2 * 8;
    const int c0 = wx * 64 + tx2 * 8;
    const int segR = wx * 8 + tx2;
    const int segC = wy * 4 + ty2;

    if (tid < 128) {
        Gr[tid] = fmaf(ta.gr[mat][j0 + tid], k1, kb);
        Gc[tid] = fmaf(ta.gc[mat][i0 + tid], k1, kb);
    }
    __syncthreads();

    uint4 w[8];
    #pragma unroll
    for (int p = 0; p < 8; p++)
        w[p] = *(const uint4*)(C + (size_t)(i0 + r0 + p) * NPTS + j0 + c0);

    const float kq = -k1 * QINV;
    float G[8];
    #pragma unroll
    for (int q = 0; q < 8; q++) G[q] = Gr[c0 + q];

    float mc[8], sc[8];
    #pragma unroll
    for (int q = 0; q < 8; q++) { mc[q] = -1e30f; sc[q] = 0.0f; }

    #pragma unroll
    for (int p = 0; p < 8; p++) {
        uint4 wq = w[p];
        float d0 = dec_lo(wq.x), d1 = dec_hi(wq.x);
        float d2 = dec_lo(wq.y), d3 = dec_hi(wq.y);
        float d4 = dec_lo(wq.z), d5 = dec_hi(wq.z);
        float d6 = dec_lo(wq.w), d7 = dec_hi(wq.w);

        float t0 = fmaf(d0, kq, G[0]), t1 = fmaf(d1, kq, G[1]);
        float t2 = fmaf(d2, kq, G[2]), t3 = fmaf(d3, kq, G[3]);
        float t4 = fmaf(d4, kq, G[4]), t5 = fmaf(d5, kq, G[5]);
        float t6 = fmaf(d6, kq, G[6]), t7 = fmaf(d7, kq, G[7]);
        float mp = fmaxf(fmaxf(fmaxf(t0, t1), fmaxf(t2, t3)),
                         fmaxf(fmaxf(t4, t5), fmaxf(t6, t7)));
        float sp = ex2_fast(t0 - mp) + ex2_fast(t1 - mp)
                 + ex2_fast(t2 - mp) + ex2_fast(t3 - mp)
                 + ex2_fast(t4 - mp) + ex2_fast(t5 - mp)
                 + ex2_fast(t6 - mp) + ex2_fast(t7 - mp);
        partR[r0 + p][segR] = make_float2(mp, sp);

        float gcp = Gc[r0 + p];
        float u0 = fmaf(d0, kq, gcp), u1 = fmaf(d1, kq, gcp);
        float u2 = fmaf(d2, kq, gcp), u3 = fmaf(d3, kq, gcp);
        float u4 = fmaf(d4, kq, gcp), u5 = fmaf(d5, kq, gcp);
        float u6 = fmaf(d6, kq, gcp), u7 = fmaf(d7, kq, gcp);
        float ug = fmaxf(fmaxf(fmaxf(u0, u1), fmaxf(u2, u3)),
                         fmaxf(fmaxf(u4, u5), fmaxf(u6, u7)));
        float mn = fminf(fminf(fminf(mc[0], mc[1]), fminf(mc[2], mc[3])),
                         fminf(fminf(mc[4], mc[5]), fminf(mc[6], mc[7])));
        if (ug > mn - SKIP_BITS) {
            ms_upd(mc[0], sc[0], u0); ms_upd(mc[1], sc[1], u1);
            ms_upd(mc[2], sc[2], u2); ms_upd(mc[3], sc[3], u3);
            ms_upd(mc[4], sc[4], u4); ms_upd(mc[5], sc[5], u5);
            ms_upd(mc[6], sc[6], u6); ms_upd(mc[7], sc[7], u7);
        }
    }
    #pragma unroll
    for (int q = 0; q < 8; q++) partC[c0 + q][segC] = make_float2(mc[q], sc[q]);
    __syncthreads();

    if (tid < 128) {
        float2 pr[16];
        #pragma unroll
        for (int k = 0; k < 16; k++) pr[k] = partR[tid][k];
        float M = pr[0].x;
        #pragma unroll
        for (int k = 1; k < 16; k++) M = fmaxf(M, pr[k].x);
        float S = 0.0f;
        #pragma unroll
        for (int k = 0; k < 16; k++) S = fmaf(pr[k].y, ex2_fast(pr[k].x - M), S);
        ta.Pr[mat][(size_t)bj * NPTS + i0 + tid] = make_float2(M, S);
    } else if (!diag) {
        int j = tid - 128;
        float2 pc[16];
        #pragma unroll
        for (int k = 0; k < 16; k++) pc[k] = partC[j][k];
        float M = pc[0].x;
        #pragma unroll
        for (int k = 1; k < 16; k++) M = fmaxf(M, pc[k].x);
        float S = 0.0f;
        #pragma unroll
        for (int k = 0; k < 16; k++) S = fmaf(pc[k].y, ex2_fast(pc[k].x - M), S);
        ta.Pc[mat][(size_t)bi * NPTS + j0 + j] = make_float2(M, S);
    }
}

// ---------------------------------------------------------------------------
// Stage 2: combine 64 partials/row; optional score capture.
// ---------------------------------------------------------------------------
struct S2 {
    const float2* P[4];
    float* g[4];
    int gslot[4];
};

__global__ void __launch_bounds__(128)
stage2_all(S2 s2, float eps, int avg, int slot, int store_score) {
    const int a = blockIdx.y;
    const int lane = threadIdx.x & 31;
    const int part = threadIdx.x >> 5;
    const int r = blockIdx.x * 32 + lane;
    const float2* __restrict__ P = s2.P[a] + (size_t)part * 16 * NPTS + r;

    float2 p[16];
    #pragma unroll
    for (int k = 0; k < 16; k++) p[k] = P[(size_t)k * NPTS];
    float M = p[0].x;
    #pragma unroll
    for (int k = 1; k < 16; k++) M = fmaxf(M, p[k].x);
    float S = 0.0f;
    #pragma unroll
    for (int k = 0; k < 16; k++) S = fmaf(p[k].y, ex2_fast(p[k].x - M), S);

    __shared__ float sm_m[4][33], sm_s[4][33];
    sm_m[part][lane] = M;
    sm_s[part][lane] = S;
    __syncthreads();

    if (threadIdx.x < 32) {
        float m0 = sm_m[0][lane], m1 = sm_m[1][lane];
        float m2 = sm_m[2][lane], m3 = sm_m[3][lane];
        float Mx = fmaxf(fmaxf(m0, m1), fmaxf(m2, m3));
        float Sx = sm_s[0][lane] * ex2_fast(m0 - Mx)
                 + sm_s[1][lane] * ex2_fast(m1 - Mx)
                 + sm_s[2][lane] * ex2_fast(m2 - Mx)
                 + sm_s[3][lane] * ex2_fast(m3 - Mx);
        float val = -eps * LN2_F * (Mx + lg2_fast(Sx));
        if (avg) val = 0.5f * (s2.g[a][r] + val);
        s2.g[a][r] = val;

        if (store_score)
            d_score[a * NPTS + r] = (Mx - KB_CONST) * eps * LN2_F;

        float vmx = val;
        #pragma unroll
        for (int o = 16; o > 0; o >>= 1)
            vmx = fmaxf(vmx, __shfl_xor_sync(0xffffffffu, vmx, o));
        if (lane == 0)
            atomicMax(&d_stat_max[slot * 4 + s2.gslot[a]], enc_f(vmx));
    }
}

// ---------------------------------------------------------------------------
// collect score-relative candidate lists — integer domain, group early-out.
// ---------------------------------------------------------------------------
#define PUSH(d, row, idx, qcv) do {                                           \
    unsigned pos = atomicAdd(&d_cnt[(d) * NPTS + (row)], 1u);                 \
    if (pos < KCAP)                                                           \
        d_list[((size_t)(d) * NPTS + (row)) * KCAP + pos] =                   \
            ((unsigned)(idx) << 16) | (qcv);                                  \
} while (0)

__global__ void __launch_bounds__(256)
collect_lists(const unsigned short* __restrict__ cq,
              const float* __restrict__ gab, const float* __restrict__ fba,
              const float* __restrict__ faa, const float* __restrict__ gbb) {
    const int mz = blockIdx.z;
    int bi = blockIdx.y, bj = blockIdx.x;
    if (mz > 0 && bi > bj) return;
    const unsigned short* C = cq + (size_t)mz * NN;
    const int i0 = bi * 128, j0 = bj * 128;
    const int dirR = (mz == 0) ? 0 : mz + 1;
    const int dirC = (mz == 0) ? 1 : dirR;
    const bool doCol = (mz == 0) || (bi != bj);
    const float* grow = (mz == 0) ? gab : ((mz == 1) ? faa : gbb);
    const float* gcol = (mz == 0) ? fba : ((mz == 1) ? faa : gbb);

    __shared__ int thrRq[128], thrCq[128], gjq[128], giq[128];
    const int tid = threadIdx.x;
    if (tid < 128) {
        thrRq[tid] = (int)floorf((d_score[dirR * NPTS + i0 + tid] - T_UNITS) * QSCALE);
        thrCq[tid] = (int)floorf((d_score[dirC * NPTS + j0 + tid] - T_UNITS) * QSCALE);
        gjq[tid] = (int)ceilf(grow[j0 + tid] * QSCALE);
        giq[tid] = (int)ceilf(gcol[i0 + tid] * QSCALE);
    }
    __syncthreads();

    const int lane = tid & 31, warp = tid >> 5;
    const int wy = warp >> 1, wx = warp & 1;
    const int ty2 = lane & 3, tx2 = lane >> 2;
    const int r0 = wy * 32 + ty2 * 8;
    const int c0 = wx * 64 + tx2 * 8;

    int g8[8], gqmax8 = -0x7fffffff, thrCmin8 = 0x7fffffff;
    #pragma unroll
    for (int q = 0; q < 8; q++) {
        g8[q] = gjq[c0 + q];
        gqmax8 = max(gqmax8, g8[q]);
        thrCmin8 = min(thrCmin8, thrCq[c0 + q]);
    }
    int thrC8[8];
    #pragma unroll
    for (int q = 0; q < 8; q++) thrC8[q] = thrCq[c0 + q];

    #pragma unroll
    for (int p = 0; p < 8; p++) {
        const int rl = r0 + p;
        uint4 wq = *(const uint4*)(C + (size_t)(i0 + rl) * NPTS + j0 + c0);

        unsigned m01 = __vminu2(wq.x, wq.y);
        unsigned m23 = __vminu2(wq.z, wq.w);
        unsigned mm  = __vminu2(m01, m23);
        int minqc = (int)min(mm & 0xffffu, mm >> 16);

        const int thrRrl = thrRq[rl];
        const int girl   = giq[rl];
        int cap = gqmax8 - thrRrl;
        if (doCol) cap = max(cap, girl - thrCmin8);

        if (minqc <= cap) {
            unsigned qc[8];
            qc[0] = wq.x & 0xffffu; qc[1] = wq.x >> 16;
            qc[2] = wq.y & 0xffffu; qc[3] = wq.y >> 16;
            qc[4] = wq.z & 0xffffu; qc[5] = wq.z >> 16;
            qc[6] = wq.w & 0xffffu; qc[7] = wq.w >> 16;
            #pragma unroll
            for (int q = 0; q < 8; q++) {
                if ((int)qc[q] <= g8[q] - thrRrl)
                    PUSH(dirR, i0 + rl, j0 + c0 + q, qc[q]);
                if (doCol && (int)qc[q] <= girl - thrC8[q])
                    PUSH(dirC, j0 + c0 + q, i0 + rl, qc[q]);
            }
        }
    }
}

// ---------------------------------------------------------------------------
// Sparse softmin over candidate lists (single pass). Dense fallback only on
// KCAP overflow (should never fire with T=10/KCAP=768).
// ---------------------------------------------------------------------------
struct SP {
    const float* gw[4];
    float* out[4];
    const unsigned short* mat[4];
};

__global__ void __launch_bounds__(256)
sparse_softmin(SP sp, float k1, float kb, float eps) {
    const int dir = blockIdx.y;
    const int warp = threadIdx.x >> 5, lane = threadIdx.x & 31;

    const float* __restrict__ g = sp.gw[dir];
    const unsigned* __restrict__ lst = d_list + (size_t)dir * NPTS * KCAP;
    const float kq = -k1 * QINV;

    #pragma unroll
    for (int rr = 0; rr < 4; rr++) {
        const int r = blockIdx.x * 32 + warp * 4 + rr;
        const unsigned c = d_cnt[dir * NPTS + r];
        float m = -1e30f, s = 0.0f;
        if (c <= KCAP) {
            const unsigned* __restrict__ L = lst + (size_t)r * KCAP;
            for (unsigned k = lane; k < c; k += 32) {
                unsigned e = L[k];
                float t = fmaf(g[e >> 16], k1, fmaf((float)(e & 0xffffu), kq, kb));
                ms_upd(m, s, t);
            }
        } else {
            const unsigned short* __restrict__ Cm = sp.mat[dir];
            float m4[4] = {-1e30f, -1e30f, -1e30f, -1e30f};
            float s4[4] = {0.0f, 0.0f, 0.0f, 0.0f};
            int it = 0;
            for (int j = lane; j < NPTS; j += 32, it++) {
                size_t off;
                if (dir == 0)      off = (size_t)r * NPTS + j;
                else if (dir == 1) off = (size_t)j * NPTS + r;
                else               off = (j >= r) ? (size_t)r * NPTS + j
                                                  : (size_t)j * NPTS + r;
                float t = fmaf(g[j], k1, fmaf((float)Cm[off], kq, kb));
                int a = it & 3;
                ms_upd(m4[a], s4[a], t);
            }
            m = m4[0]; s = s4[0];
            #pragma unroll
            for (int a = 1; a < 4; a++) {
                float Mx = fmaxf(m, m4[a]);
                s = s * ex2_fast(m - Mx) + s4[a] * ex2_fast(m4[a] - Mx);
                m = Mx;
            }
        }
        #pragma unroll
        for (int o = 16; o > 0; o >>= 1) {
            float m2 = __shfl_xor_sync(0xffffffffu, m, o);
            float s2 = __shfl_xor_sync(0xffffffffu, s, o);
            float Mx = fmaxf(m, m2);
            s = s * ex2_fast(m - Mx) + s2 * ex2_fast(m2 - Mx);
            m = Mx;
        }
        if (lane == 0)
            sp.out[dir][r] = -eps * LN2_F * (m + lg2_fast(s));
    }
}

// ---------------------------------------------------------------------------
__global__ void __launch_bounds__(256)
update_avg(float* __restrict__ fba, const float* __restrict__ ft,
           float* __restrict__ gab, const float* __restrict__ gt,
           float* __restrict__ faa, const float* __restrict__ fs,
           float* __restrict__ gbb, const float* __restrict__ gs) {
    const int i = blockIdx.x * 256 + threadIdx.x;
    fba[i] = 0.5f * (fba[i] + ft[i]);
    gab[i] = 0.5f * (gab[i] + gt[i]);
    faa[i] = 0.5f * (faa[i] + fs[i]);
    gbb[i] = 0.5f * (gbb[i] + gs[i]);
}

// ---------------------------------------------------------------------------
__global__ void final_kernel(const float* __restrict__ fbf, const float* __restrict__ faf,
                             const float* __restrict__ gaf, const float* __restrict__ gbf,
                             float* __restrict__ out) {
    __shared__ float sh[256];
    float s = 0.0f;
    for (int i = threadIdx.x; i < NPTS; i += 256)
        s += (fbf[i] - faf[i]) + (gaf[i] - gbf[i]);
    sh[threadIdx.x] = s;
    __syncthreads();
    #pragma unroll
    for (int o = 128; o > 0; o >>= 1) {
        if (threadIdx.x < o) sh[threadIdx.x] += sh[threadIdx.x + o];
        __syncthreads();
    }
    if (threadIdx.x == 0) out[0] = sh[0] * (1.0f / (float)NPTS);
}

// ---------------------------------------------------------------------------
extern "C" void kernel_launch(void* const* d_in, const int* in_sizes, int n_in,
                              void* d_out, int out_size) {
    (void)in_sizes; (void)n_in; (void)out_size;
    const float* x = (const float*)d_in[0];
    const float* y = (const float*)d_in[1];
    float* out = (float*)d_out;

    unsigned short* cq = nullptr;
    float2* part = nullptr;
    float *vec = nullptr, *tmin = nullptr;
    cudaGetSymbolAddress((void**)&cq,   d_cq);
    cudaGetSymbolAddress((void**)&part, d_part);
    cudaGetSymbolAddress((void**)&vec,  d_vecbuf);
    cudaGetSymbolAddress((void**)&tmin, d_tilemin);

    unsigned short* Cxy = cq;
    unsigned short* Cxx = cq + NN;
    unsigned short* Cyy = cq + 2 * NN;
    float2* Pft = part;
    float2* Pgt = part + (size_t)NCHUNK * NPTS;
    float2* Pfs = part + 2 * (size_t)NCHUNK * NPTS;
    float2* Pgs = part + 3 * (size_t)NCHUNK * NPTS;

    float* hx   = vec + (size_t)V_HX   * NPTS;
    float* hy   = vec + (size_t)V_HY   * NPTS;
    float* zero = vec + (size_t)V_ZERO * NPTS;
    float* faa  = vec + (size_t)V_FAA  * NPTS;
    float* gbb  = vec + (size_t)V_GBB  * NPTS;
    float* gab  = vec + (size_t)V_GAB  * NPTS;
    float* fba  = vec + (size_t)V_FBA  * NPTS;
    float* ft   = vec + (size_t)V_FT   * NPTS;
    float* gt   = vec + (size_t)V_GT   * NPTS;
    float* fs   = vec + (size_t)V_FS   * NPTS;
    float* gs   = vec + (size_t)V_GS   * NPTS;

    static const float EPS[11] = {1024.0f, 256.0f, 64.0f, 16.0f, 4.0f, 1.0f,
                                  0.25f, 0.0625f, 0.015625f, 0.00390625f, 0.0025f};

    init_misc_kernel<<<128, 256>>>();
    prep_kernel<<<2048, 256>>>(x, y, hx, hy);
    gemm_cost_q<<<dim3(64, 64, 3), 256>>>(x, y, hx, hy, cq, tmin);

    TA init_ta, ta;
    init_ta.C[0] = Cxy; init_ta.C[1] = Cxx; init_ta.C[2] = Cyy;
    init_ta.tmin[0] = tmin; init_ta.tmin[1] = tmin + 4096; init_ta.tmin[2] = tmin + 8192;
    init_ta.Pr[0] = Pft; init_ta.Pc[0] = Pgt;
    init_ta.Pr[1] = Pfs; init_ta.Pc[1] = Pfs;
    init_ta.Pr[2] = Pgs; init_ta.Pc[2] = Pgs;
    init_ta.rslot[0] = 0; init_ta.cslot[0] = 1;
    init_ta.rslot[1] = 2; init_ta.cslot[1] = 2;
    init_ta.rslot[2] = 3; init_ta.cslot[2] = 3;
    for (int m = 0; m < 3; m++) { init_ta.gr[m] = zero; init_ta.gc[m] = zero; }
    ta = init_ta;
    ta.gr[0] = gab; ta.gc[0] = fba;
    ta.gr[1] = faa; ta.gc[1] = faa;
    ta.gr[2] = gbb; ta.gc[2] = gbb;

    S2 s2_loop;
    s2_loop.P[0] = Pft; s2_loop.P[1] = Pgt; s2_loop.P[2] = Pfs; s2_loop.P[3] = Pgs;
    s2_loop.g[0] = fba; s2_loop.g[1] = gab; s2_loop.g[2] = faa; s2_loop.g[3] = gbb;
    s2_loop.gslot[0] = 1; s2_loop.gslot[1] = 0; s2_loop.gslot[2] = 2; s2_loop.gslot[3] = 3;

    SP sp;
    sp.gw[0] = gab; sp.gw[1] = fba; sp.gw[2] = faa; sp.gw[3] = gbb;
    sp.out[0] = ft; sp.out[1] = gt; sp.out[2] = fs; sp.out[3] = gs;
    sp.mat[0] = Cxy; sp.mat[1] = Cxy; sp.mat[2] = Cxx; sp.mat[3] = Cyy;

    dim3 s2g(256, 4);
    dim3 spg(256, 4);
    const float KB = KB_CONST;

    {   // init round: eps0 = 1024, g = 0 (stats slot 0 = enc(0))
        float e0 = EPS[0];
        tile_softmin_A<<<NTILES_ALL, 256>>>(init_ta, LOG2E_F / e0, KB, 0);
        stage2_all<<<s2g, 128>>>(s2_loop, e0, 0, 1, 0);
    }

    for (int it = 0; it < 11; it++) {
        float e = EPS[it];
        float k1 = LOG2E_F / e;
        int cslot = it + 1, pslot = it + 2;
        if (e >= 1.0f) {
            tile_softmin_A<<<NTILES_ALL, 256>>>(ta, k1, KB, cslot);
            stage2_all<<<s2g, 128>>>(s2_loop, e, 1, pslot, 0);
        } else if (e >= 0.25f) {
            tile_softmin_B<<<NTILES_ALL, 256>>>(ta, k1, KB);
            stage2_all<<<s2g, 128>>>(s2_loop, e, 1, pslot, 1);   // capture scores
            collect_lists<<<dim3(64, 64, 3), 256>>>(cq, gab, fba, faa, gbb);
        } else {
            sparse_softmin<<<spg, 256>>>(sp, k1, KB, e);
            update_avg<<<32, 256>>>(fba, ft, gab, gt, faa, fs, gbb, gs);
        }
    }

    {   // final non-averaged extrapolation at eps = blur^p (sparse)
        float ef = EPS[10];
        sparse_softmin<<<spg, 256>>>(sp, LOG2E_F / ef, KB, ef);
    }

    final_kernel<<<1, 256>>>(ft, fs, gt, gs, out);
}